// round 3
// baseline (speedup 1.0000x reference)
#include <cuda_runtime.h>

#define B_   2
#define S_   2048
#define DM_  1024
#define NH_  16
#define DK_  64
#define BH_  (B_*NH_)

// Scratch (device globals — no allocation allowed in kernel_launch)
__device__ float g_q[(size_t)BH_ * S_ * DK_];    // [b,h,s,d]
__device__ float g_k[(size_t)BH_ * S_ * DK_];
__device__ float g_v[(size_t)BH_ * S_ * DK_];
__device__ float g_ctx[(size_t)B_ * S_ * DM_];   // [b,s,h*64+d]

// ---------------------------------------------------------------------------
// 128x128x8 fp32 SGEMM, 256 threads, 8x8 per thread (split 64-offset frags).
// MODE 0: A from param; scatter output col n -> (h=n/64, d=n%64) into g_q/k/v.
// MODE 1: A = g_ctx (bound IN DEVICE CODE — never pass device globals from
//         host!); plain row-major store into C.
// ---------------------------------------------------------------------------
template<int MODE, int DEST>
__global__ __launch_bounds__(256)
void gemm128(const float* __restrict__ Ain, const float* __restrict__ W,
             float* __restrict__ C)
{
    constexpr int K = DM_, N = DM_;
    const float* __restrict__ A = (MODE == 1) ? (const float*)g_ctx : Ain;

    __shared__ float As[8][128];
    __shared__ float Bs[8][128];

    const int tid = threadIdx.x;
    const int tx  = tid & 15;        // 0..15  -> n frag
    const int ty  = tid >> 4;        // 0..15  -> m frag
    const int m0  = blockIdx.y * 128;
    const int n0  = blockIdx.x * 128;

    float acc[8][8];
#pragma unroll
    for (int i = 0; i < 8; i++)
#pragma unroll
        for (int j = 0; j < 8; j++) acc[i][j] = 0.f;

    const int arow = tid >> 1;          // 0..127
    const int acol = (tid & 1) * 4;     // 0 or 4
    const int brow = tid >> 5;          // 0..7
    const int bcol = (tid & 31) * 4;    // 0..124

    const float* Aptr = A + (size_t)(m0 + arow) * K + acol;
    const float* Wptr = W + (size_t)brow * N + n0 + bcol;

    for (int k0 = 0; k0 < K; k0 += 8) {
        float4 av = *(const float4*)(Aptr + k0);
        float4 bv = *(const float4*)(Wptr + (size_t)k0 * N);
        As[acol + 0][arow] = av.x;
        As[acol + 1][arow] = av.y;
        As[acol + 2][arow] = av.z;
        As[acol + 3][arow] = av.w;
        *(float4*)&Bs[brow][bcol] = bv;
        __syncthreads();

#pragma unroll
        for (int k = 0; k < 8; k++) {
            float a[8], b[8];
            *(float4*)&a[0] = *(const float4*)&As[k][ty * 4];
            *(float4*)&a[4] = *(const float4*)&As[k][64 + ty * 4];
            *(float4*)&b[0] = *(const float4*)&Bs[k][tx * 4];
            *(float4*)&b[4] = *(const float4*)&Bs[k][64 + tx * 4];
#pragma unroll
            for (int i = 0; i < 8; i++)
#pragma unroll
                for (int j = 0; j < 8; j++)
                    acc[i][j] = fmaf(a[i], b[j], acc[i][j]);
        }
        __syncthreads();
    }

    // Epilogue
#pragma unroll
    for (int i = 0; i < 8; i++) {
        const int gm = m0 + ((i < 4) ? (ty * 4 + i) : (64 + ty * 4 + (i - 4)));
#pragma unroll
        for (int j = 0; j < 8; j++) {
            const int gc = n0 + ((j < 4) ? (tx * 4 + j) : (64 + tx * 4 + (j - 4)));
            if (MODE == 1) {
                C[(size_t)gm * N + gc] = acc[i][j];
            } else {
                float* dst = (DEST == 0) ? g_q : (DEST == 1) ? g_k : g_v;
                const int b = gm >> 11, s = gm & (S_ - 1);
                const int h = gc >> 6,  d = gc & 63;
                dst[(((size_t)(b * NH_ + h)) * S_ + s) * DK_ + d] = acc[i][j];
            }
        }
    }
}

// ---------------------------------------------------------------------------
// Flash attention, fp32, causal. One block = 128 query rows of one (b,h).
// One thread = one query row; q[64] and acc[64] live in registers.
// KV tiles of 32 rows staged in SMEM, read broadcast (all lanes same addr).
// ---------------------------------------------------------------------------
__global__ __launch_bounds__(128)
void attn_kernel()
{
    __shared__ float Ks[32][64];
    __shared__ float Vs[32][64];

    const int tid = threadIdx.x;
    const int bh  = blockIdx.y;            // b*16 + h
    const int q0  = blockIdx.x * 128;
    const int row = q0 + tid;

    const float* Qp = g_q + ((size_t)bh * S_ + row) * DK_;
    const float* Kb = g_k + (size_t)bh * S_ * DK_;
    const float* Vb = g_v + (size_t)bh * S_ * DK_;

    float q[64], acc[64];
#pragma unroll
    for (int i = 0; i < 16; i++) ((float4*)q)[i] = ((const float4*)Qp)[i];
#pragma unroll
    for (int d = 0; d < 64; d++) acc[d] = 0.f;

    float mx = -1e30f, l = 0.f;
    const int kv_end = q0 + 128;   // causal: nothing beyond the q tile

    for (int j0 = 0; j0 < kv_end; j0 += 32) {
        __syncthreads();
        // stage 32x64 K and V tiles (512 float4 each, 4 per thread)
#pragma unroll
        for (int i = 0; i < 4; i++) {
            const int li = i * 128 + tid;
            const int j = li >> 4, d4 = li & 15;
            ((float4*)Ks[j])[d4] = ((const float4*)(Kb + (size_t)(j0 + j) * DK_))[d4];
            ((float4*)Vs[j])[d4] = ((const float4*)(Vb + (size_t)(j0 + j) * DK_))[d4];
        }
        __syncthreads();

        float s[32];
#pragma unroll
        for (int j = 0; j < 32; j++) {
            const float4* kr = (const float4*)Ks[j];
            float s0 = 0.f, s1 = 0.f, s2 = 0.f, s3 = 0.f;
#pragma unroll
            for (int k4 = 0; k4 < 16; k4++) {
                float4 f = kr[k4];
                s0 = fmaf(q[k4 * 4 + 0], f.x, s0);
                s1 = fmaf(q[k4 * 4 + 1], f.y, s1);
                s2 = fmaf(q[k4 * 4 + 2], f.z, s2);
                s3 = fmaf(q[k4 * 4 + 3], f.w, s3);
            }
            s[j] = ((s0 + s1) + (s2 + s3)) * 0.125f;   // 1/sqrt(64)
        }

        // causal mask (only tiles touching/past the diagonal)
        if (j0 + 31 > row) {
#pragma unroll
            for (int j = 0; j < 32; j++)
                if (j0 + j > row) s[j] = -1e30f;
        }

        float mt = s[0];
#pragma unroll
        for (int j = 1; j < 32; j++) mt = fmaxf(mt, s[j]);
        const float mnew = fmaxf(mx, mt);
        const float corr = __expf(mx - mnew);
        l *= corr;
#pragma unroll
        for (int d = 0; d < 64; d++) acc[d] *= corr;

        float ps = 0.f;
#pragma unroll
        for (int j = 0; j < 32; j++) {
            const float p = __expf(s[j] - mnew);
            s[j] = p;
            ps += p;
        }
        l += ps;
        mx = mnew;

#pragma unroll
        for (int j = 0; j < 32; j++) {
            const float p = s[j];
            const float4* vr = (const float4*)Vs[j];
#pragma unroll
            for (int d4 = 0; d4 < 16; d4++) {
                float4 f = vr[d4];
                acc[d4 * 4 + 0] = fmaf(p, f.x, acc[d4 * 4 + 0]);
                acc[d4 * 4 + 1] = fmaf(p, f.y, acc[d4 * 4 + 1]);
                acc[d4 * 4 + 2] = fmaf(p, f.z, acc[d4 * 4 + 2]);
                acc[d4 * 4 + 3] = fmaf(p, f.w, acc[d4 * 4 + 3]);
            }
        }
    }

    const float inv = 1.0f / l;
    const int b = bh >> 4, h = bh & 15;
    float* dst = g_ctx + ((size_t)(b * S_ + row)) * DM_ + h * DK_;
#pragma unroll
    for (int d4 = 0; d4 < 16; d4++) {
        float4 f;
        f.x = acc[d4 * 4 + 0] * inv;
        f.y = acc[d4 * 4 + 1] * inv;
        f.z = acc[d4 * 4 + 2] * inv;
        f.w = acc[d4 * 4 + 3] * inv;
        ((float4*)dst)[d4] = f;
    }
}

// ---------------------------------------------------------------------------
// inputs (metadata order): input_Q, input_K, input_V, attn_mask, flag,
//                          W_Q, W_K, W_V, W_O
// attn_mask/flag ignored: mask is a fixed causal mask handled analytically.
// ---------------------------------------------------------------------------
extern "C" void kernel_launch(void* const* d_in, const int* in_sizes, int n_in,
                              void* d_out, int out_size)
{
    const float* xq = (const float*)d_in[0];
    const float* xk = (const float*)d_in[1];
    const float* xv = (const float*)d_in[2];
    const float* wq = (const float*)d_in[5];
    const float* wk = (const float*)d_in[6];
    const float* wv = (const float*)d_in[7];
    const float* wo = (const float*)d_in[8];
    float* out = (float*)d_out;

    dim3 gg(DM_ / 128, (B_ * S_) / 128);   // (8, 32)
    gemm128<0, 0><<<gg, 256>>>(xq, wq, nullptr);
    gemm128<0, 1><<<gg, 256>>>(xk, wk, nullptr);
    gemm128<0, 2><<<gg, 256>>>(xv, wv, nullptr);

    attn_kernel<<<dim3(S_ / 128, BH_), 128>>>();

    // out = g_ctx @ W_O  (A bound to g_ctx inside the kernel, MODE==1)
    gemm128<1, 0><<<gg, 256>>>(nullptr, wo, out);
}

// round 6
// speedup vs baseline: 1.4193x; 1.4193x over previous
#include <cuda_runtime.h>
#include <cuda_bf16.h>
#include <cstdint>

#define B_   2
#define S_   2048
#define DM_  1024
#define NH_  16
#define DK_  64
#define BH_  (B_*NH_)
#define M_TOT 4096   // B_*S_

// ---------------- device scratch ----------------
__device__ float g_q[(size_t)BH_ * S_ * DK_];    // [b,h,s,d] fp32
__device__ float g_k[(size_t)BH_ * S_ * DK_];
__device__ float g_v[(size_t)BH_ * S_ * DK_];
__device__ float g_ctx[(size_t)B_ * S_ * DM_];   // [b,s,h*64+d] fp32

// bf16 hi/lo split. a slots: 0=xq 1=xk 2=xv 3=ctx ; w slots 0..3 = WQ,WK,WV,WO ([n][k])
__device__ __nv_bfloat16 g_ahi[4][(size_t)M_TOT * DM_];
__device__ __nv_bfloat16 g_alo[4][(size_t)M_TOT * DM_];
__device__ __nv_bfloat16 g_whi[4][(size_t)DM_ * DM_];
__device__ __nv_bfloat16 g_wlo[4][(size_t)DM_ * DM_];

// ---------------- helpers (all baseline PTX, sm_80+: safe on compute_103) ----
__device__ __forceinline__ uint32_t smem_u32(const void* p) {
    uint32_t a;
    asm("{ .reg .u64 t; cvta.to.shared.u64 t, %1; cvt.u32.u64 %0, t; }" : "=r"(a) : "l"(p));
    return a;
}
__device__ __forceinline__ void cp16(uint32_t s, const void* g) {
    asm volatile("cp.async.cg.shared.global [%0], [%1], 16;" :: "r"(s), "l"(g) : "memory");
}
#define CP_COMMIT() asm volatile("cp.async.commit_group;" ::: "memory")
#define CP_WAIT1()  asm volatile("cp.async.wait_group 1;" ::: "memory")

__device__ __forceinline__ void ldm4(uint32_t* r, uint32_t a) {
    asm volatile("ldmatrix.sync.aligned.m8n8.x4.shared.b16 {%0,%1,%2,%3}, [%4];"
                 : "=r"(r[0]), "=r"(r[1]), "=r"(r[2]), "=r"(r[3]) : "r"(a));
}
__device__ __forceinline__ void mma_bf16(float* d, const uint32_t* a, uint32_t b0, uint32_t b1) {
    asm volatile("mma.sync.aligned.m16n8k16.row.col.f32.bf16.bf16.f32 "
                 "{%0,%1,%2,%3}, {%4,%5,%6,%7}, {%8,%9}, {%0,%1,%2,%3};"
                 : "+f"(d[0]), "+f"(d[1]), "+f"(d[2]), "+f"(d[3])
                 : "r"(a[0]), "r"(a[1]), "r"(a[2]), "r"(a[3]), "r"(b0), "r"(b1));
}

__device__ __forceinline__ void split_bf16(float x, __nv_bfloat16& hi, __nv_bfloat16& lo) {
    hi = __float2bfloat16(x);
    lo = __float2bfloat16(x - __bfloat162float(hi));
}

// ---------------- convert kernels ----------------
__global__ __launch_bounds__(256)
void conv_a3(const float* __restrict__ s0, const float* __restrict__ s1,
             const float* __restrict__ s2)
{
    const int z = blockIdx.z;
    const float* src = (z == 0) ? s0 : (z == 1) ? s1 : s2;
    const size_t i4 = ((size_t)blockIdx.x * 256 + threadIdx.x) * 4;
    float4 v = *(const float4*)(src + i4);
    __nv_bfloat16 h0,l0,h1,l1,h2,l2,h3,l3;
    split_bf16(v.x,h0,l0); split_bf16(v.y,h1,l1); split_bf16(v.z,h2,l2); split_bf16(v.w,h3,l3);
    __nv_bfloat162* ph = (__nv_bfloat162*)(&g_ahi[z][i4]);
    __nv_bfloat162* pl = (__nv_bfloat162*)(&g_alo[z][i4]);
    ph[0] = __nv_bfloat162(h0,h1); ph[1] = __nv_bfloat162(h2,h3);
    pl[0] = __nv_bfloat162(l0,l1); pl[1] = __nv_bfloat162(l2,l3);
}

__global__ __launch_bounds__(256)
void conv_actx()
{
    const size_t i4 = ((size_t)blockIdx.x * 256 + threadIdx.x) * 4;
    float4 v = *(const float4*)(g_ctx + i4);
    __nv_bfloat16 h0,l0,h1,l1,h2,l2,h3,l3;
    split_bf16(v.x,h0,l0); split_bf16(v.y,h1,l1); split_bf16(v.z,h2,l2); split_bf16(v.w,h3,l3);
    __nv_bfloat162* ph = (__nv_bfloat162*)(&g_ahi[3][i4]);
    __nv_bfloat162* pl = (__nv_bfloat162*)(&g_alo[3][i4]);
    ph[0] = __nv_bfloat162(h0,h1); ph[1] = __nv_bfloat162(h2,h3);
    pl[0] = __nv_bfloat162(l0,l1); pl[1] = __nv_bfloat162(l2,l3);
}

// weights: W [k][n] fp32 -> transposed bf16 hi/lo [n][k]; blockIdx.z = which
__global__ __launch_bounds__(256)
void conv_w(const float* __restrict__ w0, const float* __restrict__ w1,
            const float* __restrict__ w2, const float* __restrict__ w3)
{
    const int z = blockIdx.z;
    const float* W = (z == 0) ? w0 : (z == 1) ? w1 : (z == 2) ? w2 : w3;
    __shared__ float tile[32][33];
    const int tx = threadIdx.x & 31;
    const int ty = threadIdx.x >> 5;      // 0..7
    const int kx = blockIdx.x * 32;
    const int nx = blockIdx.y * 32;
#pragma unroll
    for (int i = 0; i < 4; i++)
        tile[ty + 8*i][tx] = W[(size_t)(kx + ty + 8*i) * DM_ + nx + tx];
    __syncthreads();
#pragma unroll
    for (int i = 0; i < 4; i++) {
        const float x = tile[tx][ty + 8*i];
        __nv_bfloat16 h, l;
        split_bf16(x, h, l);
        const size_t o = (size_t)(nx + ty + 8*i) * DM_ + kx + tx;
        g_whi[z][o] = h;
        g_wlo[z][o] = l;
    }
}

// ---------------------------------------------------------------------------
// mma.sync bf16-split GEMM. 128x128 tile, 256 thr (8 warps, 32x64 each),
// K-chunk 32, 3-stage cp.async ring. 3 passes: AhBh + AhBl + AlBh (fp32 acc).
// SMEM rows padded to 80B: 16B-aligned, conflict-free for ldmatrix/cp.async.
// MODE 0: scatter to g_q/g_k/g_v per a_slot. MODE 1: row-major to C.
// ---------------------------------------------------------------------------
#define SSTR 80
#define TS   (128 * SSTR)     // 10240 bytes per tile
#define BUFS (4 * TS)         // Ah, Al, Bh, Bl
#define GEMM_SMEM (3 * BUFS)  // 122880

template<int MODE>
__global__ __launch_bounds__(256)
void gemm_mma(int a_slot, int w_slot, float* __restrict__ C)
{
    extern __shared__ char smem[];
    const uint32_t sb = smem_u32(smem);
    const int tid  = threadIdx.x;
    const int lane = tid & 31, wid = tid >> 5;
    const int wm = wid >> 1, wn = wid & 1;            // warp grid 4(m) x 2(n)
    const int m0 = blockIdx.y * 128, n0 = blockIdx.x * 128;

    const __nv_bfloat16* __restrict__ Ahp = g_ahi[a_slot] + (size_t)m0 * DM_;
    const __nv_bfloat16* __restrict__ Alp = g_alo[a_slot] + (size_t)m0 * DM_;
    const __nv_bfloat16* __restrict__ Bhp = g_whi[w_slot] + (size_t)n0 * DM_;
    const __nv_bfloat16* __restrict__ Blp = g_wlo[w_slot] + (size_t)n0 * DM_;

    float acc[2][8][4];
#pragma unroll
    for (int i = 0; i < 2; i++)
#pragma unroll
        for (int j = 0; j < 8; j++)
#pragma unroll
            for (int t = 0; t < 4; t++) acc[i][j][t] = 0.f;

    // ldmatrix per-lane base offsets (bytes within a tile)
    const int rr = lane & 7, q = lane >> 3;
    const uint32_t a_base = (uint32_t)((wm*32 + rr + (q & 1)*8) * SSTR + (q >> 1)*16);
    const uint32_t b_base = (uint32_t)((wn*64 + (q >> 1)*8 + rr) * SSTR + (q & 1)*16);

    auto load_chunk = [&](int c, int buf) {
        const int k0 = c * 32;
        const uint32_t bufb = sb + (uint32_t)buf * BUFS;
#pragma unroll
        for (int it = 0; it < 2; it++) {
            const int row = it * 64 + (tid >> 2);
            const int seg = tid & 3;
            const size_t go = (size_t)row * DM_ + k0 + seg * 8;
            const uint32_t so = (uint32_t)(row * SSTR + seg * 16);
            cp16(bufb + 0*TS + so, Ahp + go);
            cp16(bufb + 1*TS + so, Alp + go);
            cp16(bufb + 2*TS + so, Bhp + go);
            cp16(bufb + 3*TS + so, Blp + go);
        }
    };

    load_chunk(0, 0); CP_COMMIT();
    load_chunk(1, 1); CP_COMMIT();

    for (int c = 0; c < DM_ / 32; c++) {
        CP_WAIT1();                // chunk c landed (always-commit keeps count uniform)
        __syncthreads();

        const uint32_t bufb = sb + (uint32_t)(c % 3) * BUFS;
        const uint32_t Ah_s = bufb, Al_s = bufb + TS, Bh_s = bufb + 2*TS, Bl_s = bufb + 3*TS;

#pragma unroll
        for (int s = 0; s < 2; s++) {
            const uint32_t ko = (uint32_t)s * 32;
            uint32_t ah[2][4], al[2][4], bb[4];
            ldm4(ah[0], Ah_s + a_base + ko);
            ldm4(ah[1], Ah_s + a_base + 16*SSTR + ko);
#pragma unroll
            for (int jp = 0; jp < 4; jp++) {           // pass 1: Ah * Bh
                ldm4(bb, Bh_s + b_base + (uint32_t)jp*16*SSTR + ko);
                mma_bf16(acc[0][2*jp],   ah[0], bb[0], bb[1]);
                mma_bf16(acc[0][2*jp+1], ah[0], bb[2], bb[3]);
                mma_bf16(acc[1][2*jp],   ah[1], bb[0], bb[1]);
                mma_bf16(acc[1][2*jp+1], ah[1], bb[2], bb[3]);
            }
#pragma unroll
            for (int jp = 0; jp < 4; jp++) {           // pass 2: Ah * Bl
                ldm4(bb, Bl_s + b_base + (uint32_t)jp*16*SSTR + ko);
                mma_bf16(acc[0][2*jp],   ah[0], bb[0], bb[1]);
                mma_bf16(acc[0][2*jp+1], ah[0], bb[2], bb[3]);
                mma_bf16(acc[1][2*jp],   ah[1], bb[0], bb[1]);
                mma_bf16(acc[1][2*jp+1], ah[1], bb[2], bb[3]);
            }
            ldm4(al[0], Al_s + a_base + ko);
            ldm4(al[1], Al_s + a_base + 16*SSTR + ko);
#pragma unroll
            for (int jp = 0; jp < 4; jp++) {           // pass 3: Al * Bh
                ldm4(bb, Bh_s + b_base + (uint32_t)jp*16*SSTR + ko);
                mma_bf16(acc[0][2*jp],   al[0], bb[0], bb[1]);
                mma_bf16(acc[0][2*jp+1], al[0], bb[2], bb[3]);
                mma_bf16(acc[1][2*jp],   al[1], bb[0], bb[1]);
                mma_bf16(acc[1][2*jp+1], al[1], bb[2], bb[3]);
            }
        }

        __syncthreads();
        if (c + 2 < DM_ / 32) load_chunk(c + 2, (c + 2) % 3);
        CP_COMMIT();               // always commit (possibly empty group)
    }

    // epilogue: c0,c1 -> (row, col..col+1); c2,c3 -> (row+8, ...)
    const int r_in = lane >> 2;
    const int c_in = (lane & 3) * 2;
#pragma unroll
    for (int i = 0; i < 2; i++) {
        const int mb = m0 + wm*32 + i*16 + r_in;
#pragma unroll
        for (int j = 0; j < 8; j++) {
            const int col = n0 + wn*64 + j*8 + c_in;
            if (MODE == 1) {
                *(float2*)(C + (size_t)mb * DM_ + col)       = make_float2(acc[i][j][0], acc[i][j][1]);
                *(float2*)(C + (size_t)(mb + 8) * DM_ + col) = make_float2(acc[i][j][2], acc[i][j][3]);
            } else {
                float* base = (a_slot == 0) ? g_q : (a_slot == 1) ? g_k : g_v;
                const int h = col >> 6, d = col & 63;
                const int b0i = mb >> 11, s0i = mb & (S_ - 1);
                *(float2*)(base + (((size_t)(b0i*NH_ + h))*S_ + s0i)*DK_ + d)
                    = make_float2(acc[i][j][0], acc[i][j][1]);
                const int mb2 = mb + 8;
                const int b1i = mb2 >> 11, s1i = mb2 & (S_ - 1);
                *(float2*)(base + (((size_t)(b1i*NH_ + h))*S_ + s1i)*DK_ + d)
                    = make_float2(acc[i][j][2], acc[i][j][3]);
            }
        }
    }
}

// ---------------------------------------------------------------------------
// Flash attention fp32, causal. 256 threads: lane pair (l, l^16) shares a
// q-row, each lane handles 32 of 64 dims (halves regs -> higher occupancy).
// ---------------------------------------------------------------------------
__global__ __launch_bounds__(256)
void attn_kernel()
{
    __shared__ float Ks[32][64];
    __shared__ float Vs[32][64];

    const int tid  = threadIdx.x;
    const int half = (tid >> 4) & 1;
    const int lrow = (tid & 15) | ((tid >> 5) << 4);   // 0..127
    const int bh   = blockIdx.y;
    const int q0   = blockIdx.x * 128;
    const int row  = q0 + lrow;

    const float* Qp = g_q + ((size_t)bh * S_ + row) * DK_ + half * 32;
    const float* Kb = g_k + (size_t)bh * S_ * DK_;
    const float* Vb = g_v + (size_t)bh * S_ * DK_;

    float q[32], acc[32];
#pragma unroll
    for (int i = 0; i < 8; i++) ((float4*)q)[i] = ((const float4*)Qp)[i];
#pragma unroll
    for (int d = 0; d < 32; d++) acc[d] = 0.f;

    float mx = -1e30f, l = 0.f;
    const int kv_end = q0 + 128;

    for (int j0 = 0; j0 < kv_end; j0 += 32) {
        __syncthreads();
#pragma unroll
        for (int i = 0; i < 2; i++) {
            const int li = i * 256 + tid;
            const int j = li >> 4, d4 = li & 15;
            ((float4*)Ks[j])[d4] = ((const float4*)(Kb + (size_t)(j0 + j) * DK_))[d4];
            ((float4*)Vs[j])[d4] = ((const float4*)(Vb + (size_t)(j0 + j) * DK_))[d4];
        }
        __syncthreads();

        float s[32];
#pragma unroll
        for (int j = 0; j < 32; j++) {
            const float4* kr = (const float4*)(&Ks[j][half * 32]);
            float s0 = 0.f, s1 = 0.f, s2 = 0.f, s3 = 0.f;
#pragma unroll
            for (int k4 = 0; k4 < 8; k4++) {
                float4 f = kr[k4];
                s0 = fmaf(q[k4 * 4 + 0], f.x, s0);
                s1 = fmaf(q[k4 * 4 + 1], f.y, s1);
                s2 = fmaf(q[k4 * 4 + 2], f.z, s2);
                s3 = fmaf(q[k4 * 4 + 3], f.w, s3);
            }
            const float part = (s0 + s1) + (s2 + s3);
            s[j] = (part + __shfl_xor_sync(0xffffffffu, part, 16)) * 0.125f;
        }

        if (j0 + 31 > row) {
#pragma unroll
            for (int j = 0; j < 32; j++)
                if (j0 + j > row) s[j] = -1e30f;
        }

        float mt = s[0];
#pragma unroll
        for (int j = 1; j < 32; j++) mt = fmaxf(mt, s[j]);
        const float mnew = fmaxf(mx, mt);
        const float corr = __expf(mx - mnew);
        l *= corr;
#pragma unroll
        for (int d = 0; d < 32; d++) acc[d] *= corr;

        float ps = 0.f;
#pragma unroll
        for (int j = 0; j < 32; j++) {
            const float p = __expf(s[j] - mnew);
            s[j] = p;
            ps += p;
        }
        l += ps;
        mx = mnew;

#pragma unroll
        for (int j = 0; j < 32; j++) {
            const float p = s[j];
            const float4* vr = (const float4*)(&Vs[j][half * 32]);
#pragma unroll
            for (int d4 = 0; d4 < 8; d4++) {
                float4 f = vr[d4];
                acc[d4 * 4 + 0] = fmaf(p, f.x, acc[d4 * 4 + 0]);
                acc[d4 * 4 + 1] = fmaf(p, f.y, acc[d4 * 4 + 1]);
                acc[d4 * 4 + 2] = fmaf(p, f.z, acc[d4 * 4 + 2]);
                acc[d4 * 4 + 3] = fmaf(p, f.w, acc[d4 * 4 + 3]);
            }
        }
    }

    const float inv = 1.0f / l;
    const int b = bh >> 4, h = bh & 15;
    float* dst = g_ctx + ((size_t)(b * S_ + row)) * DM_ + h * DK_ + half * 32;
#pragma unroll
    for (int d4 = 0; d4 < 8; d4++) {
        float4 f;
        f.x = acc[d4 * 4 + 0] * inv;
        f.y = acc[d4 * 4 + 1] * inv;
        f.z = acc[d4 * 4 + 2] * inv;
        f.w = acc[d4 * 4 + 3] * inv;
        ((float4*)dst)[d4] = f;
    }
}

// ---------------------------------------------------------------------------
extern "C" void kernel_launch(void* const* d_in, const int* in_sizes, int n_in,
                              void* d_out, int out_size)
{
    const float* xq = (const float*)d_in[0];
    const float* xk = (const float*)d_in[1];
    const float* xv = (const float*)d_in[2];
    const float* wq = (const float*)d_in[5];
    const float* wk = (const float*)d_in[6];
    const float* wv = (const float*)d_in[7];
    const float* wo = (const float*)d_in[8];
    float* out = (float*)d_out;

    cudaFuncSetAttribute(gemm_mma<0>, cudaFuncAttributeMaxDynamicSharedMemorySize, GEMM_SMEM);
    cudaFuncSetAttribute(gemm_mma<1>, cudaFuncAttributeMaxDynamicSharedMemorySize, GEMM_SMEM);

    conv_w<<<dim3(DM_ / 32, DM_ / 32, 4), 256>>>(wq, wk, wv, wo);
    conv_a3<<<dim3((M_TOT * DM_) / (256 * 4), 1, 3), 256>>>(xq, xk, xv);

    dim3 gg(DM_ / 128, M_TOT / 128);   // (8, 32)
    gemm_mma<0><<<gg, 256, GEMM_SMEM>>>(0, 0, nullptr);
    gemm_mma<0><<<gg, 256, GEMM_SMEM>>>(1, 1, nullptr);
    gemm_mma<0><<<gg, 256, GEMM_SMEM>>>(2, 2, nullptr);

    attn_kernel<<<dim3(S_ / 128, BH_), 256>>>();

    conv_actx<<<(M_TOT * DM_) / (256 * 4), 256>>>();
    gemm_mma<1><<<gg, 256, GEMM_SMEM>>>(3, 3, out);
}

// round 7
// speedup vs baseline: 2.9069x; 2.0481x over previous
#include <cuda_runtime.h>
#include <cuda_bf16.h>
#include <cstdint>

#define B_   2
#define S_   2048
#define DM_  1024
#define NH_  16
#define DK_  64
#define BH_  (B_*NH_)
#define M_TOT 4096   // B_*S_

// ---------------- device scratch ----------------
// bf16 hi/lo split GEMM inputs. a slots: 0=xq 1=xk 2=xv 3=ctx ; w slots 0..3 ([n][k])
__device__ __nv_bfloat16 g_ahi[4][(size_t)M_TOT * DM_];
__device__ __nv_bfloat16 g_alo[4][(size_t)M_TOT * DM_];
__device__ __nv_bfloat16 g_whi[4][(size_t)DM_ * DM_];
__device__ __nv_bfloat16 g_wlo[4][(size_t)DM_ * DM_];
// split Q/K/V in [b,h,s,d] (Q pre-scaled by 1/8)
__device__ __nv_bfloat16 g_qhi[(size_t)BH_ * S_ * DK_];
__device__ __nv_bfloat16 g_qlo[(size_t)BH_ * S_ * DK_];
__device__ __nv_bfloat16 g_khi[(size_t)BH_ * S_ * DK_];
__device__ __nv_bfloat16 g_klo[(size_t)BH_ * S_ * DK_];
__device__ __nv_bfloat16 g_vhi[(size_t)BH_ * S_ * DK_];
__device__ __nv_bfloat16 g_vlo[(size_t)BH_ * S_ * DK_];

// ---------------- helpers (baseline PTX, sm_80-level: safe on compute_103) ---
__device__ __forceinline__ uint32_t smem_u32(const void* p) {
    uint32_t a;
    asm("{ .reg .u64 t; cvta.to.shared.u64 t, %1; cvt.u32.u64 %0, t; }" : "=r"(a) : "l"(p));
    return a;
}
__device__ __forceinline__ void cp16(uint32_t s, const void* g) {
    asm volatile("cp.async.cg.shared.global [%0], [%1], 16;" :: "r"(s), "l"(g) : "memory");
}
#define CP_COMMIT() asm volatile("cp.async.commit_group;" ::: "memory")
#define CP_WAIT1()  asm volatile("cp.async.wait_group 1;" ::: "memory")

__device__ __forceinline__ void ldm4(uint32_t* r, uint32_t a) {
    asm volatile("ldmatrix.sync.aligned.m8n8.x4.shared.b16 {%0,%1,%2,%3}, [%4];"
                 : "=r"(r[0]), "=r"(r[1]), "=r"(r[2]), "=r"(r[3]) : "r"(a));
}
__device__ __forceinline__ void ldm4t(uint32_t* r, uint32_t a) {
    asm volatile("ldmatrix.sync.aligned.m8n8.x4.trans.shared.b16 {%0,%1,%2,%3}, [%4];"
                 : "=r"(r[0]), "=r"(r[1]), "=r"(r[2]), "=r"(r[3]) : "r"(a));
}
__device__ __forceinline__ void mma_bf16(float* d, const uint32_t* a, uint32_t b0, uint32_t b1) {
    asm volatile("mma.sync.aligned.m16n8k16.row.col.f32.bf16.bf16.f32 "
                 "{%0,%1,%2,%3}, {%4,%5,%6,%7}, {%8,%9}, {%0,%1,%2,%3};"
                 : "+f"(d[0]), "+f"(d[1]), "+f"(d[2]), "+f"(d[3])
                 : "r"(a[0]), "r"(a[1]), "r"(a[2]), "r"(a[3]), "r"(b0), "r"(b1));
}
__device__ __forceinline__ void split_bf16(float x, __nv_bfloat16& hi, __nv_bfloat16& lo) {
    hi = __float2bfloat16(x);
    lo = __float2bfloat16(x - __bfloat162float(hi));
}
__device__ __forceinline__ uint32_t pack2(__nv_bfloat16 lo16, __nv_bfloat16 hi16) {
    return (uint32_t)__bfloat16_as_ushort(lo16) | ((uint32_t)__bfloat16_as_ushort(hi16) << 16);
}
// split-pack two floats (x->low half lane, y->high) into hi-part and lo-part regs
__device__ __forceinline__ void pksplit(float x, float y, uint32_t& hi, uint32_t& lo) {
    __nv_bfloat16 hx, lx, hy, ly;
    split_bf16(x, hx, lx);
    split_bf16(y, hy, ly);
    hi = pack2(hx, hy);
    lo = pack2(lx, ly);
}

// ---------------- convert kernels ----------------
__global__ __launch_bounds__(256)
void conv_a3(const float* __restrict__ s0, const float* __restrict__ s1,
             const float* __restrict__ s2)
{
    const int z = blockIdx.z;
    const float* src = (z == 0) ? s0 : (z == 1) ? s1 : s2;
    const size_t i4 = ((size_t)blockIdx.x * 256 + threadIdx.x) * 4;
    float4 v = *(const float4*)(src + i4);
    __nv_bfloat16 h0,l0,h1,l1,h2,l2,h3,l3;
    split_bf16(v.x,h0,l0); split_bf16(v.y,h1,l1); split_bf16(v.z,h2,l2); split_bf16(v.w,h3,l3);
    uint32_t* ph = (uint32_t*)(&g_ahi[z][i4]);
    uint32_t* pl = (uint32_t*)(&g_alo[z][i4]);
    ph[0] = pack2(h0,h1); ph[1] = pack2(h2,h3);
    pl[0] = pack2(l0,l1); pl[1] = pack2(l2,l3);
}

// weights: W [k][n] fp32 -> transposed bf16 hi/lo [n][k]; blockIdx.z = which
__global__ __launch_bounds__(256)
void conv_w(const float* __restrict__ w0, const float* __restrict__ w1,
            const float* __restrict__ w2, const float* __restrict__ w3)
{
    const int z = blockIdx.z;
    const float* W = (z == 0) ? w0 : (z == 1) ? w1 : (z == 2) ? w2 : w3;
    __shared__ float tile[32][33];
    const int tx = threadIdx.x & 31;
    const int ty = threadIdx.x >> 5;      // 0..7
    const int kx = blockIdx.x * 32;
    const int nx = blockIdx.y * 32;
#pragma unroll
    for (int i = 0; i < 4; i++)
        tile[ty + 8*i][tx] = W[(size_t)(kx + ty + 8*i) * DM_ + nx + tx];
    __syncthreads();
#pragma unroll
    for (int i = 0; i < 4; i++) {
        const float x = tile[tx][ty + 8*i];
        __nv_bfloat16 h, l;
        split_bf16(x, h, l);
        const size_t o = (size_t)(nx + ty + 8*i) * DM_ + kx + tx;
        g_whi[z][o] = h;
        g_wlo[z][o] = l;
    }
}

// ---------------------------------------------------------------------------
// mma.sync bf16-split GEMM. 128x128 tile, 256 thr (8 warps 32x64), K-chunk 32,
// 3-stage cp.async ring. Passes: AhBh + AlBh (Bh reused) + AhBl.
// MODE 0: epilogue splits to g_{q,k,v}{hi,lo} [b,h,s,d] (Q scaled 1/8).
// MODE 1: row-major fp32 to C.
// ---------------------------------------------------------------------------
#define SSTR 80
#define TS   (128 * SSTR)
#define BUFS (4 * TS)
#define GEMM_SMEM (3 * BUFS)  // 122880

template<int MODE>
__global__ __launch_bounds__(256)
void gemm_mma(int a_slot, int w_slot, float* __restrict__ C)
{
    extern __shared__ char smem[];
    const uint32_t sb = smem_u32(smem);
    const int tid  = threadIdx.x;
    const int lane = tid & 31, wid = tid >> 5;
    const int wm = wid >> 1, wn = wid & 1;
    const int m0 = blockIdx.y * 128, n0 = blockIdx.x * 128;

    const __nv_bfloat16* __restrict__ Ahp = g_ahi[a_slot] + (size_t)m0 * DM_;
    const __nv_bfloat16* __restrict__ Alp = g_alo[a_slot] + (size_t)m0 * DM_;
    const __nv_bfloat16* __restrict__ Bhp = g_whi[w_slot] + (size_t)n0 * DM_;
    const __nv_bfloat16* __restrict__ Blp = g_wlo[w_slot] + (size_t)n0 * DM_;

    float acc[2][8][4];
#pragma unroll
    for (int i = 0; i < 2; i++)
#pragma unroll
        for (int j = 0; j < 8; j++)
#pragma unroll
            for (int t = 0; t < 4; t++) acc[i][j][t] = 0.f;

    const int rr = lane & 7, q = lane >> 3;
    const uint32_t a_base = (uint32_t)((wm*32 + rr + (q & 1)*8) * SSTR + (q >> 1)*16);
    const uint32_t b_base = (uint32_t)((wn*64 + (q >> 1)*8 + rr) * SSTR + (q & 1)*16);

    auto load_chunk = [&](int c, int buf) {
        const int k0 = c * 32;
        const uint32_t bufb = sb + (uint32_t)buf * BUFS;
#pragma unroll
        for (int it = 0; it < 2; it++) {
            const int row = it * 64 + (tid >> 2);
            const int seg = tid & 3;
            const size_t go = (size_t)row * DM_ + k0 + seg * 8;
            const uint32_t so = (uint32_t)(row * SSTR + seg * 16);
            cp16(bufb + 0*TS + so, Ahp + go);
            cp16(bufb + 1*TS + so, Alp + go);
            cp16(bufb + 2*TS + so, Bhp + go);
            cp16(bufb + 3*TS + so, Blp + go);
        }
    };

    load_chunk(0, 0); CP_COMMIT();
    load_chunk(1, 1); CP_COMMIT();

    for (int c = 0; c < DM_ / 32; c++) {
        CP_WAIT1();
        __syncthreads();

        const uint32_t bufb = sb + (uint32_t)(c % 3) * BUFS;
        const uint32_t Ah_s = bufb, Al_s = bufb + TS, Bh_s = bufb + 2*TS, Bl_s = bufb + 3*TS;

#pragma unroll
        for (int s = 0; s < 2; s++) {
            const uint32_t ko = (uint32_t)s * 32;
            uint32_t ah[2][4], al[2][4], bb[4];
            ldm4(ah[0], Ah_s + a_base + ko);
            ldm4(ah[1], Ah_s + a_base + 16*SSTR + ko);
            ldm4(al[0], Al_s + a_base + ko);
            ldm4(al[1], Al_s + a_base + 16*SSTR + ko);
#pragma unroll
            for (int jp = 0; jp < 4; jp++) {
                ldm4(bb, Bh_s + b_base + (uint32_t)jp*16*SSTR + ko);   // Bh: used twice
                mma_bf16(acc[0][2*jp],   ah[0], bb[0], bb[1]);
                mma_bf16(acc[0][2*jp+1], ah[0], bb[2], bb[3]);
                mma_bf16(acc[1][2*jp],   ah[1], bb[0], bb[1]);
                mma_bf16(acc[1][2*jp+1], ah[1], bb[2], bb[3]);
                mma_bf16(acc[0][2*jp],   al[0], bb[0], bb[1]);
                mma_bf16(acc[0][2*jp+1], al[0], bb[2], bb[3]);
                mma_bf16(acc[1][2*jp],   al[1], bb[0], bb[1]);
                mma_bf16(acc[1][2*jp+1], al[1], bb[2], bb[3]);
                ldm4(bb, Bl_s + b_base + (uint32_t)jp*16*SSTR + ko);   // Bl
                mma_bf16(acc[0][2*jp],   ah[0], bb[0], bb[1]);
                mma_bf16(acc[0][2*jp+1], ah[0], bb[2], bb[3]);
                mma_bf16(acc[1][2*jp],   ah[1], bb[0], bb[1]);
                mma_bf16(acc[1][2*jp+1], ah[1], bb[2], bb[3]);
            }
        }

        __syncthreads();
        if (c + 2 < DM_ / 32) load_chunk(c + 2, (c + 2) % 3);
        CP_COMMIT();
    }

    const int r_in = lane >> 2;
    const int c_in = (lane & 3) * 2;
    const float sc = (MODE == 0 && a_slot == 0) ? 0.125f : 1.0f;
#pragma unroll
    for (int i = 0; i < 2; i++) {
        const int mb = m0 + wm*32 + i*16 + r_in;
#pragma unroll
        for (int j = 0; j < 8; j++) {
            const int col = n0 + wn*64 + j*8 + c_in;
            if (MODE == 1) {
                *(float2*)(C + (size_t)mb * DM_ + col)       = make_float2(acc[i][j][0], acc[i][j][1]);
                *(float2*)(C + (size_t)(mb + 8) * DM_ + col) = make_float2(acc[i][j][2], acc[i][j][3]);
            } else {
                __nv_bfloat16* hb = (a_slot == 0) ? g_qhi : (a_slot == 1) ? g_khi : g_vhi;
                __nv_bfloat16* lb = (a_slot == 0) ? g_qlo : (a_slot == 1) ? g_klo : g_vlo;
                const int h = col >> 6, d = col & 63;
                uint32_t phi, plo;
#pragma unroll
                for (int half = 0; half < 2; half++) {
                    const int m2 = mb + half * 8;
                    const int bi = m2 >> 11, si = m2 & (S_ - 1);
                    const size_t off = (((size_t)(bi*NH_ + h))*S_ + si)*DK_ + d;
                    pksplit(acc[i][j][2*half] * sc, acc[i][j][2*half+1] * sc, phi, plo);
                    *(uint32_t*)(hb + off) = phi;
                    *(uint32_t*)(lb + off) = plo;
                }
            }
        }
    }
}

// ---------------------------------------------------------------------------
// mma.sync bf16-split flash attention, causal. CTA = 128 q-rows of one (b,h),
// 8 warps x 16-row strips. KV tiles 64 rows, double-buffered cp.async.
// QK: Qh*Kh + Ql*Kh + Qh*Kl ; PV: Ph*Vh + Pl*Vh + Ph*Vl (V via ldmatrix.trans).
// Output ctx written split straight into GEMM a-slot 3.
// ---------------------------------------------------------------------------
#define ASTR 144                         // 128B payload + 16B pad
#define QTILE (128 * ASTR)               // 18432
#define KVTILE (64 * ASTR)               // 9216
#define SQH 0
#define SQL QTILE
#define SKV (2 * QTILE)                  // KV stage base
#define KVSTAGE (4 * KVTILE)             // Kh,Kl,Vh,Vl = 36864
#define ATTN_SMEM (2 * QTILE + 2 * KVSTAGE)   // 110592

__global__ __launch_bounds__(256)
void attn_mma()
{
    extern __shared__ char smem[];
    const uint32_t sb = smem_u32(smem);
    const int tid = threadIdx.x, lane = tid & 31, w = tid >> 5;
    const int qt = (S_ / 128 - 1) - blockIdx.x;   // heavy tiles first
    const int bh = blockIdx.y;
    const int q0 = qt * 128;
    const int iters = (q0 + 128) / 64;            // >= 2

    const __nv_bfloat16* __restrict__ Qh = g_qhi + ((size_t)bh * S_ + q0) * DK_;
    const __nv_bfloat16* __restrict__ Ql = g_qlo + ((size_t)bh * S_ + q0) * DK_;
    const __nv_bfloat16* __restrict__ Kh = g_khi + (size_t)bh * S_ * DK_;
    const __nv_bfloat16* __restrict__ Kl = g_klo + (size_t)bh * S_ * DK_;
    const __nv_bfloat16* __restrict__ Vh = g_vhi + (size_t)bh * S_ * DK_;
    const __nv_bfloat16* __restrict__ Vl = g_vlo + (size_t)bh * S_ * DK_;

    auto ldkv = [&](int c, int buf) {
        const int j0 = c * 64;
        const uint32_t kb = sb + SKV + (uint32_t)buf * KVSTAGE;
#pragma unroll
        for (int i = 0; i < 2; i++) {
            const int e = tid + i * 256;           // 0..511
            const int r = e >> 3, sg = e & 7;
            const size_t go = (size_t)(j0 + r) * DK_ + sg * 8;
            const uint32_t so = (uint32_t)(r * ASTR + sg * 16);
            cp16(kb + 0*KVTILE + so, Kh + go);
            cp16(kb + 1*KVTILE + so, Kl + go);
            cp16(kb + 2*KVTILE + so, Vh + go);
            cp16(kb + 3*KVTILE + so, Vl + go);
        }
    };

    // stage Q (group 0) + kv0, then kv1
#pragma unroll
    for (int i = 0; i < 4; i++) {
        const int e = tid + i * 256;               // 0..1023
        const int r = e >> 3, sg = e & 7;
        const size_t go = (size_t)r * DK_ + sg * 8;
        const uint32_t so = (uint32_t)(r * ASTR + sg * 16);
        cp16(sb + SQH + so, Qh + go);
        cp16(sb + SQL + so, Ql + go);
    }
    ldkv(0, 0); CP_COMMIT();
    ldkv(1, 1); CP_COMMIT();

    const int rr = lane & 7, qq = lane >> 3;
    // A-frag base for Q (row-major), within warp strip
    const uint32_t qa_base = (uint32_t)((w*16 + rr + (qq & 1)*8) * ASTR + (qq >> 1)*16);
    // B-frag base for K (n-major rows)
    const uint32_t kb_row = (uint32_t)(((qq >> 1)*8 + rr) * ASTR + (qq & 1)*16);
    // trans B-frag base for V (k-major rows)
    const uint32_t vb_row = (uint32_t)(((qq & 1)*8 + rr) * ASTR + (qq >> 1)*16);

    uint32_t qh[4][4], ql[4][4];
    float ctx[8][4];
#pragma unroll
    for (int j = 0; j < 8; j++)
#pragma unroll
        for (int t = 0; t < 4; t++) ctx[j][t] = 0.f;
    float m1 = -1e30f, m2 = -1e30f, l1 = 0.f, l2 = 0.f;

    const int r1g = q0 + w*16 + (lane >> 2);
    const int r2g = r1g + 8;

    for (int c = 0; c < iters; c++) {
        CP_WAIT1();
        __syncthreads();
        if (c == 0) {
#pragma unroll
            for (int ks = 0; ks < 4; ks++) {
                ldm4(qh[ks], sb + SQH + qa_base + ks*32);
                ldm4(ql[ks], sb + SQL + qa_base + ks*32);
            }
        }
        const uint32_t kb = sb + SKV + (uint32_t)(c & 1) * KVSTAGE;

        // ---- S = Q K^T (3-pass split) ----
        float s[8][4];
#pragma unroll
        for (int j = 0; j < 8; j++)
#pragma unroll
            for (int t = 0; t < 4; t++) s[j][t] = 0.f;

#pragma unroll
        for (int ks = 0; ks < 4; ks++) {
#pragma unroll
            for (int jn = 0; jn < 4; jn++) {
                uint32_t kh4[4], kl4[4];
                const uint32_t off = (uint32_t)(jn*16*ASTR) + kb_row + ks*32;
                ldm4(kh4, kb + 0*KVTILE + off);
                mma_bf16(s[2*jn],   qh[ks], kh4[0], kh4[1]);
                mma_bf16(s[2*jn+1], qh[ks], kh4[2], kh4[3]);
                mma_bf16(s[2*jn],   ql[ks], kh4[0], kh4[1]);
                mma_bf16(s[2*jn+1], ql[ks], kh4[2], kh4[3]);
                ldm4(kl4, kb + 1*KVTILE + off);
                mma_bf16(s[2*jn],   qh[ks], kl4[0], kl4[1]);
                mma_bf16(s[2*jn+1], qh[ks], kl4[2], kl4[3]);
            }
        }

        // ---- causal mask ----
        const int j0 = c * 64;
        if (j0 + 63 > r1g) {
#pragma unroll
            for (int j = 0; j < 8; j++) {
                const int cg = j0 + j*8 + (lane & 3)*2;
                if (cg     > r1g) s[j][0] = -1e30f;
                if (cg + 1 > r1g) s[j][1] = -1e30f;
                if (cg     > r2g) s[j][2] = -1e30f;
                if (cg + 1 > r2g) s[j][3] = -1e30f;
            }
        }

        // ---- online softmax ----
        float mt1 = s[0][0], mt2 = s[0][2];
#pragma unroll
        for (int j = 0; j < 8; j++) {
            mt1 = fmaxf(mt1, fmaxf(s[j][0], s[j][1]));
            mt2 = fmaxf(mt2, fmaxf(s[j][2], s[j][3]));
        }
        mt1 = fmaxf(mt1, __shfl_xor_sync(0xffffffffu, mt1, 1));
        mt1 = fmaxf(mt1, __shfl_xor_sync(0xffffffffu, mt1, 2));
        mt2 = fmaxf(mt2, __shfl_xor_sync(0xffffffffu, mt2, 1));
        mt2 = fmaxf(mt2, __shfl_xor_sync(0xffffffffu, mt2, 2));
        const float mn1 = fmaxf(m1, mt1), mn2 = fmaxf(m2, mt2);
        const float co1 = __expf(m1 - mn1), co2 = __expf(m2 - mn2);

        float ps1 = 0.f, ps2 = 0.f;
#pragma unroll
        for (int j = 0; j < 8; j++) {
            s[j][0] = __expf(s[j][0] - mn1);
            s[j][1] = __expf(s[j][1] - mn1);
            s[j][2] = __expf(s[j][2] - mn2);
            s[j][3] = __expf(s[j][3] - mn2);
            ps1 += s[j][0] + s[j][1];
            ps2 += s[j][2] + s[j][3];
        }
        ps1 += __shfl_xor_sync(0xffffffffu, ps1, 1);
        ps1 += __shfl_xor_sync(0xffffffffu, ps1, 2);
        ps2 += __shfl_xor_sync(0xffffffffu, ps2, 1);
        ps2 += __shfl_xor_sync(0xffffffffu, ps2, 2);
        l1 = l1 * co1 + ps1;  m1 = mn1;
        l2 = l2 * co2 + ps2;  m2 = mn2;

#pragma unroll
        for (int j = 0; j < 8; j++) {
            ctx[j][0] *= co1; ctx[j][1] *= co1;
            ctx[j][2] *= co2; ctx[j][3] *= co2;
        }

        // ---- pack P into split A-frags (acc->A layout identity) ----
        uint32_t ph[4][4], pl[4][4];
#pragma unroll
        for (int ks = 0; ks < 4; ks++) {
            pksplit(s[2*ks][0],   s[2*ks][1],   ph[ks][0], pl[ks][0]);
            pksplit(s[2*ks][2],   s[2*ks][3],   ph[ks][1], pl[ks][1]);
            pksplit(s[2*ks+1][0], s[2*ks+1][1], ph[ks][2], pl[ks][2]);
            pksplit(s[2*ks+1][2], s[2*ks+1][3], ph[ks][3], pl[ks][3]);
        }

        // ---- ctx += P V (3-pass split), V via ldmatrix.trans ----
#pragma unroll
        for (int ks = 0; ks < 4; ks++) {
#pragma unroll
            for (int jd = 0; jd < 4; jd++) {
                uint32_t vh4[4], vl4[4];
                const uint32_t off = (uint32_t)(ks*16*ASTR) + vb_row + jd*32;
                ldm4t(vh4, kb + 2*KVTILE + off);
                mma_bf16(ctx[2*jd],   ph[ks], vh4[0], vh4[1]);
                mma_bf16(ctx[2*jd+1], ph[ks], vh4[2], vh4[3]);
                mma_bf16(ctx[2*jd],   pl[ks], vh4[0], vh4[1]);
                mma_bf16(ctx[2*jd+1], pl[ks], vh4[2], vh4[3]);
                ldm4t(vl4, kb + 3*KVTILE + off);
                mma_bf16(ctx[2*jd],   ph[ks], vl4[0], vl4[1]);
                mma_bf16(ctx[2*jd+1], ph[ks], vl4[2], vl4[3]);
            }
        }

        __syncthreads();
        if (c + 2 < iters) ldkv(c + 2, c & 1);
        CP_COMMIT();
    }

    // ---- epilogue: normalize, split, write to GEMM a-slot 3 ----
    const float i1 = 1.0f / l1, i2 = 1.0f / l2;
    const int b = bh >> 4, h = bh & 15;
    __nv_bfloat16* dh = g_ahi[3];
    __nv_bfloat16* dl = g_alo[3];
#pragma unroll
    for (int j = 0; j < 8; j++) {
        const int col = h*64 + j*8 + (lane & 3)*2;
        uint32_t phi, plo;
        pksplit(ctx[j][0] * i1, ctx[j][1] * i1, phi, plo);
        const size_t o1 = ((size_t)(b * S_ + r1g)) * DM_ + col;
        *(uint32_t*)(dh + o1) = phi;
        *(uint32_t*)(dl + o1) = plo;
        pksplit(ctx[j][2] * i2, ctx[j][3] * i2, phi, plo);
        const size_t o2 = ((size_t)(b * S_ + r2g)) * DM_ + col;
        *(uint32_t*)(dh + o2) = phi;
        *(uint32_t*)(dl + o2) = plo;
    }
}

// ---------------------------------------------------------------------------
extern "C" void kernel_launch(void* const* d_in, const int* in_sizes, int n_in,
                              void* d_out, int out_size)
{
    const float* xq = (const float*)d_in[0];
    const float* xk = (const float*)d_in[1];
    const float* xv = (const float*)d_in[2];
    const float* wq = (const float*)d_in[5];
    const float* wk = (const float*)d_in[6];
    const float* wv = (const float*)d_in[7];
    const float* wo = (const float*)d_in[8];
    float* out = (float*)d_out;

    cudaFuncSetAttribute(gemm_mma<0>, cudaFuncAttributeMaxDynamicSharedMemorySize, GEMM_SMEM);
    cudaFuncSetAttribute(gemm_mma<1>, cudaFuncAttributeMaxDynamicSharedMemorySize, GEMM_SMEM);
    cudaFuncSetAttribute(attn_mma,    cudaFuncAttributeMaxDynamicSharedMemorySize, ATTN_SMEM);

    conv_w<<<dim3(DM_ / 32, DM_ / 32, 4), 256>>>(wq, wk, wv, wo);
    conv_a3<<<dim3((M_TOT * DM_) / (256 * 4), 1, 3), 256>>>(xq, xk, xv);

    dim3 gg(DM_ / 128, M_TOT / 128);   // (8, 32)
    gemm_mma<0><<<gg, 256, GEMM_SMEM>>>(0, 0, nullptr);
    gemm_mma<0><<<gg, 256, GEMM_SMEM>>>(1, 1, nullptr);
    gemm_mma<0><<<gg, 256, GEMM_SMEM>>>(2, 2, nullptr);

    attn_mma<<<dim3(S_ / 128, BH_), 256, ATTN_SMEM>>>();

    gemm_mma<1><<<gg, 256, GEMM_SMEM>>>(3, 3, out);
}

// round 9
// speedup vs baseline: 3.1602x; 1.0871x over previous
#include <cuda_runtime.h>
#include <cuda_bf16.h>
#include <cstdint>

#define B_   2
#define S_   2048
#define DM_  1024
#define NH_  16
#define DK_  64
#define BH_  (B_*NH_)
#define M_TOT 4096   // B_*S_

// ---------------- device scratch ----------------
// bf16 hi/lo split GEMM inputs. a slots: 0=xq 1=xk 2=xv 3=ctx ; w slots 0..3 ([n][k])
__device__ __nv_bfloat16 g_ahi[4][(size_t)M_TOT * DM_];
__device__ __nv_bfloat16 g_alo[4][(size_t)M_TOT * DM_];
__device__ __nv_bfloat16 g_whi[4][(size_t)DM_ * DM_];
__device__ __nv_bfloat16 g_wlo[4][(size_t)DM_ * DM_];
// split Q/K/V in [b,h,s,d] (Q pre-scaled by 1/8)
__device__ __nv_bfloat16 g_qhi[(size_t)BH_ * S_ * DK_];
__device__ __nv_bfloat16 g_qlo[(size_t)BH_ * S_ * DK_];
__device__ __nv_bfloat16 g_khi[(size_t)BH_ * S_ * DK_];
__device__ __nv_bfloat16 g_klo[(size_t)BH_ * S_ * DK_];
__device__ __nv_bfloat16 g_vhi[(size_t)BH_ * S_ * DK_];
__device__ __nv_bfloat16 g_vlo[(size_t)BH_ * S_ * DK_];

// ---------------- helpers (baseline PTX, sm_80-level: safe on compute_103) ---
__device__ __forceinline__ uint32_t smem_u32(const void* p) {
    uint32_t a;
    asm("{ .reg .u64 t; cvta.to.shared.u64 t, %1; cvt.u32.u64 %0, t; }" : "=r"(a) : "l"(p));
    return a;
}
__device__ __forceinline__ void cp16(uint32_t s, const void* g) {
    asm volatile("cp.async.cg.shared.global [%0], [%1], 16;" :: "r"(s), "l"(g) : "memory");
}
#define CP_COMMIT() asm volatile("cp.async.commit_group;" ::: "memory")
#define CP_WAIT1()  asm volatile("cp.async.wait_group 1;" ::: "memory")

__device__ __forceinline__ void ldm4(uint32_t* r, uint32_t a) {
    asm volatile("ldmatrix.sync.aligned.m8n8.x4.shared.b16 {%0,%1,%2,%3}, [%4];"
                 : "=r"(r[0]), "=r"(r[1]), "=r"(r[2]), "=r"(r[3]) : "r"(a));
}
__device__ __forceinline__ void ldm4t(uint32_t* r, uint32_t a) {
    asm volatile("ldmatrix.sync.aligned.m8n8.x4.trans.shared.b16 {%0,%1,%2,%3}, [%4];"
                 : "=r"(r[0]), "=r"(r[1]), "=r"(r[2]), "=r"(r[3]) : "r"(a));
}
__device__ __forceinline__ void mma_bf16(float* d, const uint32_t* a, uint32_t b0, uint32_t b1) {
    asm volatile("mma.sync.aligned.m16n8k16.row.col.f32.bf16.bf16.f32 "
                 "{%0,%1,%2,%3}, {%4,%5,%6,%7}, {%8,%9}, {%0,%1,%2,%3};"
                 : "+f"(d[0]), "+f"(d[1]), "+f"(d[2]), "+f"(d[3])
                 : "r"(a[0]), "r"(a[1]), "r"(a[2]), "r"(a[3]), "r"(b0), "r"(b1));
}
__device__ __forceinline__ void split_bf16(float x, __nv_bfloat16& hi, __nv_bfloat16& lo) {
    hi = __float2bfloat16(x);
    lo = __float2bfloat16(x - __bfloat162float(hi));
}
__device__ __forceinline__ uint32_t pack2(__nv_bfloat16 lo16, __nv_bfloat16 hi16) {
    return (uint32_t)__bfloat16_as_ushort(lo16) | ((uint32_t)__bfloat16_as_ushort(hi16) << 16);
}
__device__ __forceinline__ void pksplit(float x, float y, uint32_t& hi, uint32_t& lo) {
    __nv_bfloat16 hx, lx, hy, ly;
    split_bf16(x, hx, lx);
    split_bf16(y, hy, ly);
    hi = pack2(hx, hy);
    lo = pack2(lx, ly);
}

// ---------------- convert kernels ----------------
__global__ __launch_bounds__(256)
void conv_a3(const float* __restrict__ s0, const float* __restrict__ s1,
             const float* __restrict__ s2)
{
    const int z = blockIdx.z;
    const float* src = (z == 0) ? s0 : (z == 1) ? s1 : s2;
    const size_t i4 = ((size_t)blockIdx.x * 256 + threadIdx.x) * 4;
    float4 v = *(const float4*)(src + i4);
    __nv_bfloat16 h0,l0,h1,l1,h2,l2,h3,l3;
    split_bf16(v.x,h0,l0); split_bf16(v.y,h1,l1); split_bf16(v.z,h2,l2); split_bf16(v.w,h3,l3);
    uint32_t* ph = (uint32_t*)(&g_ahi[z][i4]);
    uint32_t* pl = (uint32_t*)(&g_alo[z][i4]);
    ph[0] = pack2(h0,h1); ph[1] = pack2(h2,h3);
    pl[0] = pack2(l0,l1); pl[1] = pack2(l2,l3);
}

// weights: W [k][n] fp32 -> transposed bf16 hi/lo [n][k]; blockIdx.z = which
__global__ __launch_bounds__(256)
void conv_w(const float* __restrict__ w0, const float* __restrict__ w1,
            const float* __restrict__ w2, const float* __restrict__ w3)
{
    const int z = blockIdx.z;
    const float* W = (z == 0) ? w0 : (z == 1) ? w1 : (z == 2) ? w2 : w3;
    __shared__ float tile[32][33];
    const int tx = threadIdx.x & 31;
    const int ty = threadIdx.x >> 5;
    const int kx = blockIdx.x * 32;
    const int nx = blockIdx.y * 32;
#pragma unroll
    for (int i = 0; i < 4; i++)
        tile[ty + 8*i][tx] = W[(size_t)(kx + ty + 8*i) * DM_ + nx + tx];
    __syncthreads();
#pragma unroll
    for (int i = 0; i < 4; i++) {
        const float x = tile[tx][ty + 8*i];
        __nv_bfloat16 h, l;
        split_bf16(x, h, l);
        const size_t o = (size_t)(nx + ty + 8*i) * DM_ + kx + tx;
        g_whi[z][o] = h;
        g_wlo[z][o] = l;
    }
}

// ---------------------------------------------------------------------------
// mma.sync bf16-split GEMM. CTA tile 128(m) x 256(n), 8 warps 2x4, warp tile
// 64x64 (ratio 6 HMMA/LDSM vs 4 before -> higher crossbar ceiling).
// K-chunk 32, 3-stage cp.async ring. Passes: AhBh + AlBh (Bh reused) + AhBl.
// MODE 0: a_slot = blockIdx.z (QKV fused); split-epilogue to g_{q,k,v}{hi,lo}.
// MODE 1: row-major fp32 to C.
// ---------------------------------------------------------------------------
#define SSTR  80
#define ATILE (128 * SSTR)                 // 10240
#define BTILE (256 * SSTR)                 // 20480
#define STG   (2 * ATILE + 2 * BTILE)      // 61440
#define GEMM_SMEM (3 * STG)                // 184320

template<int MODE>
__global__ __launch_bounds__(256)
void gemm_mma(int a_slot_in, int w_slot_in, float* __restrict__ C)
{
    extern __shared__ char smem[];
    const uint32_t sb = smem_u32(smem);
    const int tid  = threadIdx.x;
    const int lane = tid & 31, wid = tid >> 5;
    const int wm = wid >> 2, wn = wid & 3;            // 2(m) x 4(n)
    const int m0 = blockIdx.y * 128, n0 = blockIdx.x * 256;
    const int a_slot = (MODE == 0) ? (int)blockIdx.z : a_slot_in;
    const int w_slot = (MODE == 0) ? (int)blockIdx.z : w_slot_in;

    const __nv_bfloat16* __restrict__ Ahp = g_ahi[a_slot] + (size_t)m0 * DM_;
    const __nv_bfloat16* __restrict__ Alp = g_alo[a_slot] + (size_t)m0 * DM_;
    const __nv_bfloat16* __restrict__ Bhp = g_whi[w_slot] + (size_t)n0 * DM_;
    const __nv_bfloat16* __restrict__ Blp = g_wlo[w_slot] + (size_t)n0 * DM_;

    float acc[4][8][4];
#pragma unroll
    for (int i = 0; i < 4; i++)
#pragma unroll
        for (int j = 0; j < 8; j++)
#pragma unroll
            for (int t = 0; t < 4; t++) acc[i][j][t] = 0.f;

    const int rr = lane & 7, q = lane >> 3;
    const uint32_t a_base = (uint32_t)((wm*64 + rr + (q & 1)*8) * SSTR + (q >> 1)*16);
    const uint32_t b_base = (uint32_t)((wn*64 + (q >> 1)*8 + rr) * SSTR + (q & 1)*16);

    auto load_chunk = [&](int c, int buf) {
        const int k0 = c * 32;
        const uint32_t st = sb + (uint32_t)buf * STG;
#pragma unroll
        for (int i = 0; i < 6; i++) {
            const int e = tid + i * 256;              // 0..1535
            const int row = e >> 2, seg = e & 3;
            if (row < 128) {                          // A rows
                const size_t go = (size_t)row * DM_ + k0 + seg * 8;
                const uint32_t so = (uint32_t)(row * SSTR + seg * 16);
                cp16(st + 0*ATILE + so, Ahp + go);
                cp16(st + 1*ATILE + so, Alp + go);
            } else {                                  // B rows
                const int r = row - 128;
                const size_t go = (size_t)r * DM_ + k0 + seg * 8;
                const uint32_t so = (uint32_t)(r * SSTR + seg * 16);
                cp16(st + 2*ATILE + so, Bhp + go);
                cp16(st + 2*ATILE + BTILE + so, Blp + go);
            }
        }
    };

    load_chunk(0, 0); CP_COMMIT();
    load_chunk(1, 1); CP_COMMIT();

    for (int c = 0; c < DM_ / 32; c++) {
        CP_WAIT1();
        __syncthreads();

        const uint32_t st = sb + (uint32_t)(c % 3) * STG;
        const uint32_t Ah_s = st, Al_s = st + ATILE;
        const uint32_t Bh_s = st + 2*ATILE, Bl_s = st + 2*ATILE + BTILE;

#pragma unroll
        for (int s = 0; s < 2; s++) {
            const uint32_t ko = (uint32_t)s * 32;
            uint32_t ah[4][4], al[4][4], bb[4];
#pragma unroll
            for (int f = 0; f < 4; f++) {
                ldm4(ah[f], Ah_s + a_base + (uint32_t)f*16*SSTR + ko);
                ldm4(al[f], Al_s + a_base + (uint32_t)f*16*SSTR + ko);
            }
#pragma unroll
            for (int jn = 0; jn < 4; jn++) {
                const uint32_t off = b_base + (uint32_t)jn*16*SSTR + ko;
                ldm4(bb, Bh_s + off);                 // Bh: used by ah AND al
#pragma unroll
                for (int f = 0; f < 4; f++) {
                    mma_bf16(acc[f][2*jn],   ah[f], bb[0], bb[1]);
                    mma_bf16(acc[f][2*jn+1], ah[f], bb[2], bb[3]);
                    mma_bf16(acc[f][2*jn],   al[f], bb[0], bb[1]);
                    mma_bf16(acc[f][2*jn+1], al[f], bb[2], bb[3]);
                }
                ldm4(bb, Bl_s + off);                 // Bl: ah only
#pragma unroll
                for (int f = 0; f < 4; f++) {
                    mma_bf16(acc[f][2*jn],   ah[f], bb[0], bb[1]);
                    mma_bf16(acc[f][2*jn+1], ah[f], bb[2], bb[3]);
                }
            }
        }

        __syncthreads();
        if (c + 2 < DM_ / 32) load_chunk(c + 2, (c + 2) % 3);
        CP_COMMIT();
    }

    const int r_in = lane >> 2;
    const int c_in = (lane & 3) * 2;
    const float sc = (MODE == 0 && a_slot == 0) ? 0.125f : 1.0f;
#pragma unroll
    for (int i = 0; i < 4; i++) {
        const int mb = m0 + wm*64 + i*16 + r_in;
#pragma unroll
        for (int j = 0; j < 8; j++) {
            const int col = n0 + wn*64 + j*8 + c_in;
            if (MODE == 1) {
                *(float2*)(C + (size_t)mb * DM_ + col)       = make_float2(acc[i][j][0], acc[i][j][1]);
                *(float2*)(C + (size_t)(mb + 8) * DM_ + col) = make_float2(acc[i][j][2], acc[i][j][3]);
            } else {
                __nv_bfloat16* hb = (a_slot == 0) ? g_qhi : (a_slot == 1) ? g_khi : g_vhi;
                __nv_bfloat16* lb = (a_slot == 0) ? g_qlo : (a_slot == 1) ? g_klo : g_vlo;
                const int h = col >> 6, d = col & 63;
                uint32_t phi, plo;
#pragma unroll
                for (int half = 0; half < 2; half++) {
                    const int m2 = mb + half * 8;
                    const int bi = m2 >> 11, si = m2 & (S_ - 1);
                    const size_t off = (((size_t)(bi*NH_ + h))*S_ + si)*DK_ + d;
                    pksplit(acc[i][j][2*half] * sc, acc[i][j][2*half+1] * sc, phi, plo);
                    *(uint32_t*)(hb + off) = phi;
                    *(uint32_t*)(lb + off) = plo;
                }
            }
        }
    }
}

// ---------------------------------------------------------------------------
// mma.sync bf16-split flash attention, causal. CTA = 128 q-rows of one (b,h),
// 8 warps x 16-row strips. KV tiles 64 rows, double-buffered cp.async.
// QK: Qh*Kh + Ql*Kh + Qh*Kl ; PV: Ph*Vh + Pl*Vh + Ph*Vl (V via ldmatrix.trans).
// Output ctx written split straight into GEMM a-slot 3.
// ---------------------------------------------------------------------------
#define ASTR 144
#define QTILE (128 * ASTR)
#define KVTILE (64 * ASTR)
#define SQH 0
#define SQL QTILE
#define SKV (2 * QTILE)
#define KVSTAGE (4 * KVTILE)
#define ATTN_SMEM (2 * QTILE + 2 * KVSTAGE)   // 110592

__global__ __launch_bounds__(256)
void attn_mma()
{
    extern __shared__ char smem[];
    const uint32_t sb = smem_u32(smem);
    const int tid = threadIdx.x, lane = tid & 31, w = tid >> 5;
    const int qt = (S_ / 128 - 1) - blockIdx.x;   // heavy tiles first
    const int bh = blockIdx.y;
    const int q0 = qt * 128;
    const int iters = (q0 + 128) / 64;

    const __nv_bfloat16* __restrict__ Qh = g_qhi + ((size_t)bh * S_ + q0) * DK_;
    const __nv_bfloat16* __restrict__ Ql = g_qlo + ((size_t)bh * S_ + q0) * DK_;
    const __nv_bfloat16* __restrict__ Kh = g_khi + (size_t)bh * S_ * DK_;
    const __nv_bfloat16* __restrict__ Kl = g_klo + (size_t)bh * S_ * DK_;
    const __nv_bfloat16* __restrict__ Vh = g_vhi + (size_t)bh * S_ * DK_;
    const __nv_bfloat16* __restrict__ Vl = g_vlo + (size_t)bh * S_ * DK_;

    auto ldkv = [&](int c, int buf) {
        const int j0 = c * 64;
        const uint32_t kb = sb + SKV + (uint32_t)buf * KVSTAGE;
#pragma unroll
        for (int i = 0; i < 2; i++) {
            const int e = tid + i * 256;
            const int r = e >> 3, sg = e & 7;
            const size_t go = (size_t)(j0 + r) * DK_ + sg * 8;
            const uint32_t so = (uint32_t)(r * ASTR + sg * 16);
            cp16(kb + 0*KVTILE + so, Kh + go);
            cp16(kb + 1*KVTILE + so, Kl + go);
            cp16(kb + 2*KVTILE + so, Vh + go);
            cp16(kb + 3*KVTILE + so, Vl + go);
        }
    };

#pragma unroll
    for (int i = 0; i < 4; i++) {
        const int e = tid + i * 256;
        const int r = e >> 3, sg = e & 7;
        const size_t go = (size_t)r * DK_ + sg * 8;
        const uint32_t so = (uint32_t)(r * ASTR + sg * 16);
        cp16(sb + SQH + so, Qh + go);
        cp16(sb + SQL + so, Ql + go);
    }
    ldkv(0, 0); CP_COMMIT();
    ldkv(1, 1); CP_COMMIT();

    const int rr = lane & 7, qq = lane >> 3;
    const uint32_t qa_base = (uint32_t)((w*16 + rr + (qq & 1)*8) * ASTR + (qq >> 1)*16);
    const uint32_t kb_row = (uint32_t)(((qq >> 1)*8 + rr) * ASTR + (qq & 1)*16);
    const uint32_t vb_row = (uint32_t)(((qq & 1)*8 + rr) * ASTR + (qq >> 1)*16);

    uint32_t qh[4][4], ql[4][4];
    float ctx[8][4];
#pragma unroll
    for (int j = 0; j < 8; j++)
#pragma unroll
        for (int t = 0; t < 4; t++) ctx[j][t] = 0.f;
    float m1 = -1e30f, m2 = -1e30f, l1 = 0.f, l2 = 0.f;

    const int r1g = q0 + w*16 + (lane >> 2);
    const int r2g = r1g + 8;

    for (int c = 0; c < iters; c++) {
        CP_WAIT1();
        __syncthreads();
        if (c == 0) {
#pragma unroll
            for (int ks = 0; ks < 4; ks++) {
                ldm4(qh[ks], sb + SQH + qa_base + ks*32);
                ldm4(ql[ks], sb + SQL + qa_base + ks*32);
            }
        }
        const uint32_t kb = sb + SKV + (uint32_t)(c & 1) * KVSTAGE;

        float s[8][4];
#pragma unroll
        for (int j = 0; j < 8; j++)
#pragma unroll
            for (int t = 0; t < 4; t++) s[j][t] = 0.f;

#pragma unroll
        for (int ks = 0; ks < 4; ks++) {
#pragma unroll
            for (int jn = 0; jn < 4; jn++) {
                uint32_t kh4[4], kl4[4];
                const uint32_t off = (uint32_t)(jn*16*ASTR) + kb_row + ks*32;
                ldm4(kh4, kb + 0*KVTILE + off);
                mma_bf16(s[2*jn],   qh[ks], kh4[0], kh4[1]);
                mma_bf16(s[2*jn+1], qh[ks], kh4[2], kh4[3]);
                mma_bf16(s[2*jn],   ql[ks], kh4[0], kh4[1]);
                mma_bf16(s[2*jn+1], ql[ks], kh4[2], kh4[3]);
                ldm4(kl4, kb + 1*KVTILE + off);
                mma_bf16(s[2*jn],   qh[ks], kl4[0], kl4[1]);
                mma_bf16(s[2*jn+1], qh[ks], kl4[2], kl4[3]);
            }
        }

        const int j0 = c * 64;
        if (j0 + 63 > r1g) {
#pragma unroll
            for (int j = 0; j < 8; j++) {
                const int cg = j0 + j*8 + (lane & 3)*2;
                if (cg     > r1g) s[j][0] = -1e30f;
                if (cg + 1 > r1g) s[j][1] = -1e30f;
                if (cg     > r2g) s[j][2] = -1e30f;
                if (cg + 1 > r2g) s[j][3] = -1e30f;
            }
        }

        float mt1 = s[0][0], mt2 = s[0][2];
#pragma unroll
        for (int j = 0; j < 8; j++) {
            mt1 = fmaxf(mt1, fmaxf(s[j][0], s[j][1]));
            mt2 = fmaxf(mt2, fmaxf(s[j][2], s[j][3]));
        }
        mt1 = fmaxf(mt1, __shfl_xor_sync(0xffffffffu, mt1, 1));
        mt1 = fmaxf(mt1, __shfl_xor_sync(0xffffffffu, mt1, 2));
        mt2 = fmaxf(mt2, __shfl_xor_sync(0xffffffffu, mt2, 1));
        mt2 = fmaxf(mt2, __shfl_xor_sync(0xffffffffu, mt2, 2));
        const float mn1 = fmaxf(m1, mt1), mn2 = fmaxf(m2, mt2);
        const float co1 = __expf(m1 - mn1), co2 = __expf(m2 - mn2);

        float ps1 = 0.f, ps2 = 0.f;
#pragma unroll
        for (int j = 0; j < 8; j++) {
            s[j][0] = __expf(s[j][0] - mn1);
            s[j][1] = __expf(s[j][1] - mn1);
            s[j][2] = __expf(s[j][2] - mn2);
            s[j][3] = __expf(s[j][3] - mn2);
            ps1 += s[j][0] + s[j][1];
            ps2 += s[j][2] + s[j][3];
        }
        ps1 += __shfl_xor_sync(0xffffffffu, ps1, 1);
        ps1 += __shfl_xor_sync(0xffffffffu, ps1, 2);
        ps2 += __shfl_xor_sync(0xffffffffu, ps2, 1);
        ps2 += __shfl_xor_sync(0xffffffffu, ps2, 2);
        l1 = l1 * co1 + ps1;  m1 = mn1;
        l2 = l2 * co2 + ps2;  m2 = mn2;

#pragma unroll
        for (int j = 0; j < 8; j++) {
            ctx[j][0] *= co1; ctx[j][1] *= co1;
            ctx[j][2] *= co2; ctx[j][3] *= co2;
        }

        uint32_t ph[4][4], pl[4][4];
#pragma unroll
        for (int ks = 0; ks < 4; ks++) {
            pksplit(s[2*ks][0],   s[2*ks][1],   ph[ks][0], pl[ks][0]);
            pksplit(s[2*ks][2],   s[2*ks][3],   ph[ks][1], pl[ks][1]);
            pksplit(s[2*ks+1][0], s[2*ks+1][1], ph[ks][2], pl[ks][2]);
            pksplit(s[2*ks+1][2], s[2*ks+1][3], ph[ks][3], pl[ks][3]);
        }

#pragma unroll
        for (int ks = 0; ks < 4; ks++) {
#pragma unroll
            for (int jd = 0; jd < 4; jd++) {
                uint32_t vh4[4], vl4[4];
                const uint32_t off = (uint32_t)(ks*16*ASTR) + vb_row + jd*32;
                ldm4t(vh4, kb + 2*KVTILE + off);
                mma_bf16(ctx[2*jd],   ph[ks], vh4[0], vh4[1]);
                mma_bf16(ctx[2*jd+1], ph[ks], vh4[2], vh4[3]);
                mma_bf16(ctx[2*jd],   pl[ks], vh4[0], vh4[1]);
                mma_bf16(ctx[2*jd+1], pl[ks], vh4[2], vh4[3]);
                ldm4t(vl4, kb + 3*KVTILE + off);
                mma_bf16(ctx[2*jd],   ph[ks], vl4[0], vl4[1]);
                mma_bf16(ctx[2*jd+1], ph[ks], vl4[2], vl4[3]);
            }
        }

        __syncthreads();
        if (c + 2 < iters) ldkv(c + 2, c & 1);
        CP_COMMIT();
    }

    const float i1 = 1.0f / l1, i2 = 1.0f / l2;
    const int b = bh >> 4, h = bh & 15;
    __nv_bfloat16* dh = g_ahi[3];
    __nv_bfloat16* dl = g_alo[3];
#pragma unroll
    for (int j = 0; j < 8; j++) {
        const int col = h*64 + j*8 + (lane & 3)*2;
        uint32_t phi, plo;
        pksplit(ctx[j][0] * i1, ctx[j][1] * i1, phi, plo);
        const size_t o1 = ((size_t)(b * S_ + r1g)) * DM_ + col;
        *(uint32_t*)(dh + o1) = phi;
        *(uint32_t*)(dl + o1) = plo;
        pksplit(ctx[j][2] * i2, ctx[j][3] * i2, phi, plo);
        const size_t o2 = ((size_t)(b * S_ + r2g)) * DM_ + col;
        *(uint32_t*)(dh + o2) = phi;
        *(uint32_t*)(dl + o2) = plo;
    }
}

// ---------------------------------------------------------------------------
extern "C" void kernel_launch(void* const* d_in, const int* in_sizes, int n_in,
                              void* d_out, int out_size)
{
    const float* xq = (const float*)d_in[0];
    const float* xk = (const float*)d_in[1];
    const float* xv = (const float*)d_in[2];
    const float* wq = (const float*)d_in[5];
    const float* wk = (const float*)d_in[6];
    const float* wv = (const float*)d_in[7];
    const float* wo = (const float*)d_in[8];
    float* out = (float*)d_out;

    cudaFuncSetAttribute(gemm_mma<0>, cudaFuncAttributeMaxDynamicSharedMemorySize, GEMM_SMEM);
    cudaFuncSetAttribute(gemm_mma<1>, cudaFuncAttributeMaxDynamicSharedMemorySize, GEMM_SMEM);
    cudaFuncSetAttribute(attn_mma,    cudaFuncAttributeMaxDynamicSharedMemorySize, ATTN_SMEM);

    conv_w<<<dim3(DM_ / 32, DM_ / 32, 4), 256>>>(wq, wk, wv, wo);
    conv_a3<<<dim3((M_TOT * DM_) / (256 * 4), 1, 3), 256>>>(xq, xk, xv);

    // fused QKV projections (blockIdx.z = slot)
    gemm_mma<0><<<dim3(DM_ / 256, M_TOT / 128, 3), 256, GEMM_SMEM>>>(0, 0, nullptr);

    attn_mma<<<dim3(S_ / 128, BH_), 256, ATTN_SMEM>>>();

    gemm_mma<1><<<dim3(DM_ / 256, M_TOT / 128), 256, GEMM_SMEM>>>(3, 3, out);
}

// round 10
// speedup vs baseline: 3.2422x; 1.0259x over previous
#include <cuda_runtime.h>
#include <cuda_bf16.h>
#include <cstdint>

#define B_   2
#define S_   2048
#define DM_  1024
#define NH_  16
#define DK_  64
#define BH_  (B_*NH_)
#define M_TOT 4096   // B_*S_

// ---------------- device scratch ----------------
// bf16 hi/lo split GEMM inputs. a slots: 0=xq 1=xk 2=xv 3=ctx ; w slots 0..3 ([n][k])
__device__ __nv_bfloat16 g_ahi[4][(size_t)M_TOT * DM_];
__device__ __nv_bfloat16 g_alo[4][(size_t)M_TOT * DM_];
__device__ __nv_bfloat16 g_whi[4][(size_t)DM_ * DM_];
__device__ __nv_bfloat16 g_wlo[4][(size_t)DM_ * DM_];
// split Q/K/V in [b,h,s,d] (Q pre-scaled by 1/8)
__device__ __nv_bfloat16 g_qhi[(size_t)BH_ * S_ * DK_];
__device__ __nv_bfloat16 g_qlo[(size_t)BH_ * S_ * DK_];
__device__ __nv_bfloat16 g_khi[(size_t)BH_ * S_ * DK_];
__device__ __nv_bfloat16 g_klo[(size_t)BH_ * S_ * DK_];
__device__ __nv_bfloat16 g_vhi[(size_t)BH_ * S_ * DK_];
__device__ __nv_bfloat16 g_vlo[(size_t)BH_ * S_ * DK_];

// ---------------- helpers (baseline PTX, sm_80-level: safe on compute_103) ---
__device__ __forceinline__ uint32_t smem_u32(const void* p) {
    uint32_t a;
    asm("{ .reg .u64 t; cvta.to.shared.u64 t, %1; cvt.u32.u64 %0, t; }" : "=r"(a) : "l"(p));
    return a;
}
__device__ __forceinline__ void cp16(uint32_t s, const void* g) {
    asm volatile("cp.async.cg.shared.global [%0], [%1], 16;" :: "r"(s), "l"(g) : "memory");
}
#define CP_COMMIT() asm volatile("cp.async.commit_group;" ::: "memory")
#define CP_WAIT1()  asm volatile("cp.async.wait_group 1;" ::: "memory")

__device__ __forceinline__ void ldm4(uint32_t* r, uint32_t a) {
    asm volatile("ldmatrix.sync.aligned.m8n8.x4.shared.b16 {%0,%1,%2,%3}, [%4];"
                 : "=r"(r[0]), "=r"(r[1]), "=r"(r[2]), "=r"(r[3]) : "r"(a));
}
__device__ __forceinline__ void ldm4t(uint32_t* r, uint32_t a) {
    asm volatile("ldmatrix.sync.aligned.m8n8.x4.trans.shared.b16 {%0,%1,%2,%3}, [%4];"
                 : "=r"(r[0]), "=r"(r[1]), "=r"(r[2]), "=r"(r[3]) : "r"(a));
}
__device__ __forceinline__ void mma_bf16(float* d, const uint32_t* a, uint32_t b0, uint32_t b1) {
    asm volatile("mma.sync.aligned.m16n8k16.row.col.f32.bf16.bf16.f32 "
                 "{%0,%1,%2,%3}, {%4,%5,%6,%7}, {%8,%9}, {%0,%1,%2,%3};"
                 : "+f"(d[0]), "+f"(d[1]), "+f"(d[2]), "+f"(d[3])
                 : "r"(a[0]), "r"(a[1]), "r"(a[2]), "r"(a[3]), "r"(b0), "r"(b1));
}
__device__ __forceinline__ void split_bf16(float x, __nv_bfloat16& hi, __nv_bfloat16& lo) {
    hi = __float2bfloat16(x);
    lo = __float2bfloat16(x - __bfloat162float(hi));
}
__device__ __forceinline__ uint32_t pack2(__nv_bfloat16 lo16, __nv_bfloat16 hi16) {
    return (uint32_t)__bfloat16_as_ushort(lo16) | ((uint32_t)__bfloat16_as_ushort(hi16) << 16);
}
__device__ __forceinline__ void pksplit(float x, float y, uint32_t& hi, uint32_t& lo) {
    __nv_bfloat16 hx, lx, hy, ly;
    split_bf16(x, hx, lx);
    split_bf16(y, hy, ly);
    hi = pack2(hx, hy);
    lo = pack2(lx, ly);
}

// ---------------- convert kernels ----------------
__global__ __launch_bounds__(256)
void conv_a3(const float* __restrict__ s0, const float* __restrict__ s1,
             const float* __restrict__ s2)
{
    const int z = blockIdx.z;
    const float* src = (z == 0) ? s0 : (z == 1) ? s1 : s2;
    const size_t i4 = ((size_t)blockIdx.x * 256 + threadIdx.x) * 4;
    float4 v = *(const float4*)(src + i4);
    __nv_bfloat16 h0,l0,h1,l1,h2,l2,h3,l3;
    split_bf16(v.x,h0,l0); split_bf16(v.y,h1,l1); split_bf16(v.z,h2,l2); split_bf16(v.w,h3,l3);
    uint32_t* ph = (uint32_t*)(&g_ahi[z][i4]);
    uint32_t* pl = (uint32_t*)(&g_alo[z][i4]);
    ph[0] = pack2(h0,h1); ph[1] = pack2(h2,h3);
    pl[0] = pack2(l0,l1); pl[1] = pack2(l2,l3);
}

// weights: W [k][n] fp32 -> transposed bf16 hi/lo [n][k]; blockIdx.z = which
__global__ __launch_bounds__(256)
void conv_w(const float* __restrict__ w0, const float* __restrict__ w1,
            const float* __restrict__ w2, const float* __restrict__ w3)
{
    const int z = blockIdx.z;
    const float* W = (z == 0) ? w0 : (z == 1) ? w1 : (z == 2) ? w2 : w3;
    __shared__ float tile[32][33];
    const int tx = threadIdx.x & 31;
    const int ty = threadIdx.x >> 5;
    const int kx = blockIdx.x * 32;
    const int nx = blockIdx.y * 32;
#pragma unroll
    for (int i = 0; i < 4; i++)
        tile[ty + 8*i][tx] = W[(size_t)(kx + ty + 8*i) * DM_ + nx + tx];
    __syncthreads();
#pragma unroll
    for (int i = 0; i < 4; i++) {
        const float x = tile[tx][ty + 8*i];
        __nv_bfloat16 h, l;
        split_bf16(x, h, l);
        const size_t o = (size_t)(nx + ty + 8*i) * DM_ + kx + tx;
        g_whi[z][o] = h;
        g_wlo[z][o] = l;
    }
}

// ---------------------------------------------------------------------------
// mma.sync bf16-split GEMM. CTA tile 128(m) x 256(n), 8 warps 2x4, warp tile
// 64x64. K-chunk 32, 3-stage cp.async ring. Passes: AhBh + AlBh + AhBl.
// MODE 0: a_slot = blockIdx.z (QKV fused); split-epilogue to g_{q,k,v}{hi,lo}.
// MODE 1: row-major fp32 to C.
// ---------------------------------------------------------------------------
#define SSTR  80
#define ATILE (128 * SSTR)
#define BTILE (256 * SSTR)
#define STG   (2 * ATILE + 2 * BTILE)
#define GEMM_SMEM (3 * STG)                // 184320

template<int MODE>
__global__ __launch_bounds__(256)
void gemm_mma(int a_slot_in, int w_slot_in, float* __restrict__ C)
{
    extern __shared__ char smem[];
    const uint32_t sb = smem_u32(smem);
    const int tid  = threadIdx.x;
    const int lane = tid & 31, wid = tid >> 5;
    const int wm = wid >> 2, wn = wid & 3;
    const int m0 = blockIdx.y * 128, n0 = blockIdx.x * 256;
    const int a_slot = (MODE == 0) ? (int)blockIdx.z : a_slot_in;
    const int w_slot = (MODE == 0) ? (int)blockIdx.z : w_slot_in;

    const __nv_bfloat16* __restrict__ Ahp = g_ahi[a_slot] + (size_t)m0 * DM_;
    const __nv_bfloat16* __restrict__ Alp = g_alo[a_slot] + (size_t)m0 * DM_;
    const __nv_bfloat16* __restrict__ Bhp = g_whi[w_slot] + (size_t)n0 * DM_;
    const __nv_bfloat16* __restrict__ Blp = g_wlo[w_slot] + (size_t)n0 * DM_;

    float acc[4][8][4];
#pragma unroll
    for (int i = 0; i < 4; i++)
#pragma unroll
        for (int j = 0; j < 8; j++)
#pragma unroll
            for (int t = 0; t < 4; t++) acc[i][j][t] = 0.f;

    const int rr = lane & 7, q = lane >> 3;
    const uint32_t a_base = (uint32_t)((wm*64 + rr + (q & 1)*8) * SSTR + (q >> 1)*16);
    const uint32_t b_base = (uint32_t)((wn*64 + (q >> 1)*8 + rr) * SSTR + (q & 1)*16);

    auto load_chunk = [&](int c, int buf) {
        const int k0 = c * 32;
        const uint32_t st = sb + (uint32_t)buf * STG;
#pragma unroll
        for (int i = 0; i < 6; i++) {
            const int e = tid + i * 256;
            const int row = e >> 2, seg = e & 3;
            if (row < 128) {
                const size_t go = (size_t)row * DM_ + k0 + seg * 8;
                const uint32_t so = (uint32_t)(row * SSTR + seg * 16);
                cp16(st + 0*ATILE + so, Ahp + go);
                cp16(st + 1*ATILE + so, Alp + go);
            } else {
                const int r = row - 128;
                const size_t go = (size_t)r * DM_ + k0 + seg * 8;
                const uint32_t so = (uint32_t)(r * SSTR + seg * 16);
                cp16(st + 2*ATILE + so, Bhp + go);
                cp16(st + 2*ATILE + BTILE + so, Blp + go);
            }
        }
    };

    load_chunk(0, 0); CP_COMMIT();
    load_chunk(1, 1); CP_COMMIT();

    for (int c = 0; c < DM_ / 32; c++) {
        CP_WAIT1();
        __syncthreads();

        const uint32_t st = sb + (uint32_t)(c % 3) * STG;
        const uint32_t Ah_s = st, Al_s = st + ATILE;
        const uint32_t Bh_s = st + 2*ATILE, Bl_s = st + 2*ATILE + BTILE;

#pragma unroll
        for (int s = 0; s < 2; s++) {
            const uint32_t ko = (uint32_t)s * 32;
            uint32_t ah[4][4], al[4][4], bb[4];
#pragma unroll
            for (int f = 0; f < 4; f++) {
                ldm4(ah[f], Ah_s + a_base + (uint32_t)f*16*SSTR + ko);
                ldm4(al[f], Al_s + a_base + (uint32_t)f*16*SSTR + ko);
            }
#pragma unroll
            for (int jn = 0; jn < 4; jn++) {
                const uint32_t off = b_base + (uint32_t)jn*16*SSTR + ko;
                ldm4(bb, Bh_s + off);
#pragma unroll
                for (int f = 0; f < 4; f++) {
                    mma_bf16(acc[f][2*jn],   ah[f], bb[0], bb[1]);
                    mma_bf16(acc[f][2*jn+1], ah[f], bb[2], bb[3]);
                    mma_bf16(acc[f][2*jn],   al[f], bb[0], bb[1]);
                    mma_bf16(acc[f][2*jn+1], al[f], bb[2], bb[3]);
                }
                ldm4(bb, Bl_s + off);
#pragma unroll
                for (int f = 0; f < 4; f++) {
                    mma_bf16(acc[f][2*jn],   ah[f], bb[0], bb[1]);
                    mma_bf16(acc[f][2*jn+1], ah[f], bb[2], bb[3]);
                }
            }
        }

        __syncthreads();
        if (c + 2 < DM_ / 32) load_chunk(c + 2, (c + 2) % 3);
        CP_COMMIT();
    }

    const int r_in = lane >> 2;
    const int c_in = (lane & 3) * 2;
    const float sc = (MODE == 0 && a_slot == 0) ? 0.125f : 1.0f;
#pragma unroll
    for (int i = 0; i < 4; i++) {
        const int mb = m0 + wm*64 + i*16 + r_in;
#pragma unroll
        for (int j = 0; j < 8; j++) {
            const int col = n0 + wn*64 + j*8 + c_in;
            if (MODE == 1) {
                *(float2*)(C + (size_t)mb * DM_ + col)       = make_float2(acc[i][j][0], acc[i][j][1]);
                *(float2*)(C + (size_t)(mb + 8) * DM_ + col) = make_float2(acc[i][j][2], acc[i][j][3]);
            } else {
                __nv_bfloat16* hb = (a_slot == 0) ? g_qhi : (a_slot == 1) ? g_khi : g_vhi;
                __nv_bfloat16* lb = (a_slot == 0) ? g_qlo : (a_slot == 1) ? g_klo : g_vlo;
                const int h = col >> 6, d = col & 63;
                uint32_t phi, plo;
#pragma unroll
                for (int half = 0; half < 2; half++) {
                    const int m2 = mb + half * 8;
                    const int bi = m2 >> 11, si = m2 & (S_ - 1);
                    const size_t off = (((size_t)(bi*NH_ + h))*S_ + si)*DK_ + d;
                    pksplit(acc[i][j][2*half] * sc, acc[i][j][2*half+1] * sc, phi, plo);
                    *(uint32_t*)(hb + off) = phi;
                    *(uint32_t*)(lb + off) = plo;
                }
            }
        }
    }
}

// ---------------------------------------------------------------------------
// mma.sync bf16-split flash attention, causal. CTA = 128 q-rows of one (b,h),
// 4 warps x 32-row strips (2 m16 frags/warp -> 12 MMA per K/V ldm4 pair,
// double the fragment reuse of the 8x16 layout). 128 threads, 2 CTAs/SM.
// KV tiles 64 rows, double-buffered cp.async.
// ---------------------------------------------------------------------------
#define ASTR 144
#define QTILE (128 * ASTR)
#define KVTILE (64 * ASTR)
#define SQH 0
#define SQL QTILE
#define SKV (2 * QTILE)
#define KVSTAGE (4 * KVTILE)
#define ATTN_SMEM (2 * QTILE + 2 * KVSTAGE)   // 110592

__global__ __launch_bounds__(128, 2)
void attn_mma()
{
    extern __shared__ char smem[];
    const uint32_t sb = smem_u32(smem);
    const int tid = threadIdx.x, lane = tid & 31, w = tid >> 5;   // w: 0..3
    const int qt = (S_ / 128 - 1) - blockIdx.x;   // heavy tiles first
    const int bh = blockIdx.y;
    const int q0 = qt * 128;
    const int iters = (q0 + 128) / 64;

    const __nv_bfloat16* __restrict__ Qh = g_qhi + ((size_t)bh * S_ + q0) * DK_;
    const __nv_bfloat16* __restrict__ Ql = g_qlo + ((size_t)bh * S_ + q0) * DK_;
    const __nv_bfloat16* __restrict__ Kh = g_khi + (size_t)bh * S_ * DK_;
    const __nv_bfloat16* __restrict__ Kl = g_klo + (size_t)bh * S_ * DK_;
    const __nv_bfloat16* __restrict__ Vh = g_vhi + (size_t)bh * S_ * DK_;
    const __nv_bfloat16* __restrict__ Vl = g_vlo + (size_t)bh * S_ * DK_;

    auto ldkv = [&](int c, int buf) {
        const int j0 = c * 64;
        const uint32_t kb = sb + SKV + (uint32_t)buf * KVSTAGE;
#pragma unroll
        for (int i = 0; i < 4; i++) {
            const int e = tid + i * 128;              // 0..511
            const int r = e >> 3, sg = e & 7;
            const size_t go = (size_t)(j0 + r) * DK_ + sg * 8;
            const uint32_t so = (uint32_t)(r * ASTR + sg * 16);
            cp16(kb + 0*KVTILE + so, Kh + go);
            cp16(kb + 1*KVTILE + so, Kl + go);
            cp16(kb + 2*KVTILE + so, Vh + go);
            cp16(kb + 3*KVTILE + so, Vl + go);
        }
    };

#pragma unroll
    for (int i = 0; i < 8; i++) {
        const int e = tid + i * 128;                  // 0..1023
        const int r = e >> 3, sg = e & 7;
        const size_t go = (size_t)r * DK_ + sg * 8;
        const uint32_t so = (uint32_t)(r * ASTR + sg * 16);
        cp16(sb + SQH + so, Qh + go);
        cp16(sb + SQL + so, Ql + go);
    }
    ldkv(0, 0); CP_COMMIT();
    ldkv(1, 1); CP_COMMIT();

    const int rr = lane & 7, qq = lane >> 3;
    const uint32_t qa_base = (uint32_t)((w*32 + rr + (qq & 1)*8) * ASTR + (qq >> 1)*16);
    const uint32_t kb_row = (uint32_t)(((qq >> 1)*8 + rr) * ASTR + (qq & 1)*16);
    const uint32_t vb_row = (uint32_t)(((qq & 1)*8 + rr) * ASTR + (qq >> 1)*16);

    uint32_t qh[2][4][4], ql[2][4][4];                // f = m16-frag (rows +0, +16)
    float ctx[2][8][4];
#pragma unroll
    for (int f = 0; f < 2; f++)
#pragma unroll
        for (int j = 0; j < 8; j++)
#pragma unroll
            for (int t = 0; t < 4; t++) ctx[f][j][t] = 0.f;
    float mrow[2][2] = {{-1e30f,-1e30f},{-1e30f,-1e30f}};
    float lrow[2][2] = {{0.f,0.f},{0.f,0.f}};

    const int rbase = q0 + w*32 + (lane >> 2);        // f*16 and +8 offsets below

    for (int c = 0; c < iters; c++) {
        CP_WAIT1();
        __syncthreads();
        if (c == 0) {
#pragma unroll
            for (int f = 0; f < 2; f++)
#pragma unroll
                for (int ks = 0; ks < 4; ks++) {
                    ldm4(qh[f][ks], sb + SQH + qa_base + (uint32_t)f*16*ASTR + ks*32);
                    ldm4(ql[f][ks], sb + SQL + qa_base + (uint32_t)f*16*ASTR + ks*32);
                }
        }
        const uint32_t kb = sb + SKV + (uint32_t)(c & 1) * KVSTAGE;

        // ---- S = Q K^T (3-pass split), K frags shared across both m-frags ----
        float s[2][8][4];
#pragma unroll
        for (int f = 0; f < 2; f++)
#pragma unroll
            for (int j = 0; j < 8; j++)
#pragma unroll
                for (int t = 0; t < 4; t++) s[f][j][t] = 0.f;

#pragma unroll
        for (int ks = 0; ks < 4; ks++) {
#pragma unroll
            for (int jn = 0; jn < 4; jn++) {
                uint32_t kh4[4], kl4[4];
                const uint32_t off = (uint32_t)(jn*16*ASTR) + kb_row + ks*32;
                ldm4(kh4, kb + 0*KVTILE + off);
#pragma unroll
                for (int f = 0; f < 2; f++) {
                    mma_bf16(s[f][2*jn],   qh[f][ks], kh4[0], kh4[1]);
                    mma_bf16(s[f][2*jn+1], qh[f][ks], kh4[2], kh4[3]);
                    mma_bf16(s[f][2*jn],   ql[f][ks], kh4[0], kh4[1]);
                    mma_bf16(s[f][2*jn+1], ql[f][ks], kh4[2], kh4[3]);
                }
                ldm4(kl4, kb + 1*KVTILE + off);
#pragma unroll
                for (int f = 0; f < 2; f++) {
                    mma_bf16(s[f][2*jn],   qh[f][ks], kl4[0], kl4[1]);
                    mma_bf16(s[f][2*jn+1], qh[f][ks], kl4[2], kl4[3]);
                }
            }
        }

        // ---- causal mask ----
        const int j0 = c * 64;
        if (j0 + 63 > rbase) {
#pragma unroll
            for (int f = 0; f < 2; f++) {
                const int r1g = rbase + f*16, r2g = r1g + 8;
#pragma unroll
                for (int j = 0; j < 8; j++) {
                    const int cg = j0 + j*8 + (lane & 3)*2;
                    if (cg     > r1g) s[f][j][0] = -1e30f;
                    if (cg + 1 > r1g) s[f][j][1] = -1e30f;
                    if (cg     > r2g) s[f][j][2] = -1e30f;
                    if (cg + 1 > r2g) s[f][j][3] = -1e30f;
                }
            }
        }

        // ---- online softmax + P pack (per m16-frag) ----
        uint32_t ph[2][4][4], pl[2][4][4];
#pragma unroll
        for (int f = 0; f < 2; f++) {
            float mt1 = s[f][0][0], mt2 = s[f][0][2];
#pragma unroll
            for (int j = 0; j < 8; j++) {
                mt1 = fmaxf(mt1, fmaxf(s[f][j][0], s[f][j][1]));
                mt2 = fmaxf(mt2, fmaxf(s[f][j][2], s[f][j][3]));
            }
            mt1 = fmaxf(mt1, __shfl_xor_sync(0xffffffffu, mt1, 1));
            mt1 = fmaxf(mt1, __shfl_xor_sync(0xffffffffu, mt1, 2));
            mt2 = fmaxf(mt2, __shfl_xor_sync(0xffffffffu, mt2, 1));
            mt2 = fmaxf(mt2, __shfl_xor_sync(0xffffffffu, mt2, 2));
            const float mn1 = fmaxf(mrow[f][0], mt1), mn2 = fmaxf(mrow[f][1], mt2);
            const float co1 = __expf(mrow[f][0] - mn1), co2 = __expf(mrow[f][1] - mn2);

            float ps1 = 0.f, ps2 = 0.f;
#pragma unroll
            for (int j = 0; j < 8; j++) {
                s[f][j][0] = __expf(s[f][j][0] - mn1);
                s[f][j][1] = __expf(s[f][j][1] - mn1);
                s[f][j][2] = __expf(s[f][j][2] - mn2);
                s[f][j][3] = __expf(s[f][j][3] - mn2);
                ps1 += s[f][j][0] + s[f][j][1];
                ps2 += s[f][j][2] + s[f][j][3];
            }
            ps1 += __shfl_xor_sync(0xffffffffu, ps1, 1);
            ps1 += __shfl_xor_sync(0xffffffffu, ps1, 2);
            ps2 += __shfl_xor_sync(0xffffffffu, ps2, 1);
            ps2 += __shfl_xor_sync(0xffffffffu, ps2, 2);
            lrow[f][0] = lrow[f][0] * co1 + ps1;  mrow[f][0] = mn1;
            lrow[f][1] = lrow[f][1] * co2 + ps2;  mrow[f][1] = mn2;

#pragma unroll
            for (int j = 0; j < 8; j++) {
                ctx[f][j][0] *= co1; ctx[f][j][1] *= co1;
                ctx[f][j][2] *= co2; ctx[f][j][3] *= co2;
            }

#pragma unroll
            for (int ks = 0; ks < 4; ks++) {
                pksplit(s[f][2*ks][0],   s[f][2*ks][1],   ph[f][ks][0], pl[f][ks][0]);
                pksplit(s[f][2*ks][2],   s[f][2*ks][3],   ph[f][ks][1], pl[f][ks][1]);
                pksplit(s[f][2*ks+1][0], s[f][2*ks+1][1], ph[f][ks][2], pl[f][ks][2]);
                pksplit(s[f][2*ks+1][2], s[f][2*ks+1][3], ph[f][ks][3], pl[f][ks][3]);
            }
        }

        // ---- ctx += P V (3-pass split), V frags shared across both m-frags ----
#pragma unroll
        for (int ks = 0; ks < 4; ks++) {
#pragma unroll
            for (int jd = 0; jd < 4; jd++) {
                uint32_t vh4[4], vl4[4];
                const uint32_t off = (uint32_t)(ks*16*ASTR) + vb_row + jd*32;
                ldm4t(vh4, kb + 2*KVTILE + off);
#pragma unroll
                for (int f = 0; f < 2; f++) {
                    mma_bf16(ctx[f][2*jd],   ph[f][ks], vh4[0], vh4[1]);
                    mma_bf16(ctx[f][2*jd+1], ph[f][ks], vh4[2], vh4[3]);
                    mma_bf16(ctx[f][2*jd],   pl[f][ks], vh4[0], vh4[1]);
                    mma_bf16(ctx[f][2*jd+1], pl[f][ks], vh4[2], vh4[3]);
                }
                ldm4t(vl4, kb + 3*KVTILE + off);
#pragma unroll
                for (int f = 0; f < 2; f++) {
                    mma_bf16(ctx[f][2*jd],   ph[f][ks], vl4[0], vl4[1]);
                    mma_bf16(ctx[f][2*jd+1], ph[f][ks], vl4[2], vl4[3]);
                }
            }
        }

        __syncthreads();
        if (c + 2 < iters) ldkv(c + 2, c & 1);
        CP_COMMIT();
    }

    // ---- epilogue: normalize, split, write to GEMM a-slot 3 ----
    const int b = bh >> 4, h = bh & 15;
    __nv_bfloat16* dh = g_ahi[3];
    __nv_bfloat16* dl = g_alo[3];
#pragma unroll
    for (int f = 0; f < 2; f++) {
        const float i1 = 1.0f / lrow[f][0], i2 = 1.0f / lrow[f][1];
        const int r1g = rbase + f*16, r2g = r1g + 8;
#pragma unroll
        for (int j = 0; j < 8; j++) {
            const int col = h*64 + j*8 + (lane & 3)*2;
            uint32_t phi, plo;
            pksplit(ctx[f][j][0] * i1, ctx[f][j][1] * i1, phi, plo);
            const size_t o1 = ((size_t)(b * S_ + r1g)) * DM_ + col;
            *(uint32_t*)(dh + o1) = phi;
            *(uint32_t*)(dl + o1) = plo;
            pksplit(ctx[f][j][2] * i2, ctx[f][j][3] * i2, phi, plo);
            const size_t o2 = ((size_t)(b * S_ + r2g)) * DM_ + col;
            *(uint32_t*)(dh + o2) = phi;
            *(uint32_t*)(dl + o2) = plo;
        }
    }
}

// ---------------------------------------------------------------------------
extern "C" void kernel_launch(void* const* d_in, const int* in_sizes, int n_in,
                              void* d_out, int out_size)
{
    const float* xq = (const float*)d_in[0];
    const float* xk = (const float*)d_in[1];
    const float* xv = (const float*)d_in[2];
    const float* wq = (const float*)d_in[5];
    const float* wk = (const float*)d_in[6];
    const float* wv = (const float*)d_in[7];
    const float* wo = (const float*)d_in[8];
    float* out = (float*)d_out;

    cudaFuncSetAttribute(gemm_mma<0>, cudaFuncAttributeMaxDynamicSharedMemorySize, GEMM_SMEM);
    cudaFuncSetAttribute(gemm_mma<1>, cudaFuncAttributeMaxDynamicSharedMemorySize, GEMM_SMEM);
    cudaFuncSetAttribute(attn_mma,    cudaFuncAttributeMaxDynamicSharedMemorySize, ATTN_SMEM);

    conv_w<<<dim3(DM_ / 32, DM_ / 32, 4), 256>>>(wq, wk, wv, wo);
    conv_a3<<<dim3((M_TOT * DM_) / (256 * 4), 1, 3), 256>>>(xq, xk, xv);

    // fused QKV projections (blockIdx.z = slot)
    gemm_mma<0><<<dim3(DM_ / 256, M_TOT / 128, 3), 256, GEMM_SMEM>>>(0, 0, nullptr);

    attn_mma<<<dim3(S_ / 128, BH_), 128, ATTN_SMEM>>>();

    gemm_mma<1><<<dim3(DM_ / 256, M_TOT / 128), 256, GEMM_SMEM>>>(3, 3, out);
}

// round 14
// speedup vs baseline: 3.5629x; 1.0989x over previous
#include <cuda_runtime.h>
#include <cuda_bf16.h>
#include <cuda_fp16.h>
#include <cstdint>

#define B_   2
#define S_   2048
#define DM_  1024
#define NH_  16
#define DK_  64
#define BH_  (B_*NH_)
#define M_TOT 4096   // B_*S_

// ---------------- device scratch ----------------
// bf16 hi/lo split GEMM inputs. a slots: 0=xq 1=xk 2=xv 3=ctx ; w slots 0..3 ([n][k])
__device__ __nv_bfloat16 g_ahi[4][(size_t)M_TOT * DM_];
__device__ __nv_bfloat16 g_alo[4][(size_t)M_TOT * DM_];
__device__ __nv_bfloat16 g_whi[4][(size_t)DM_ * DM_];
__device__ __nv_bfloat16 g_wlo[4][(size_t)DM_ * DM_];
// split Q/K in bf16 [b,h,s,d] (Q pre-scaled by 1/8); V split in FP16 hi/lo
__device__ __nv_bfloat16 g_qhi[(size_t)BH_ * S_ * DK_];
__device__ __nv_bfloat16 g_qlo[(size_t)BH_ * S_ * DK_];
__device__ __nv_bfloat16 g_khi[(size_t)BH_ * S_ * DK_];
__device__ __nv_bfloat16 g_klo[(size_t)BH_ * S_ * DK_];
__device__ __half        g_vhi[(size_t)BH_ * S_ * DK_];
__device__ __half        g_vlo[(size_t)BH_ * S_ * DK_];

// ---------------- helpers (baseline PTX, sm_80-level: safe on compute_103) ---
__device__ __forceinline__ uint32_t smem_u32(const void* p) {
    uint32_t a;
    asm("{ .reg .u64 t; cvta.to.shared.u64 t, %1; cvt.u32.u64 %0, t; }" : "=r"(a) : "l"(p));
    return a;
}
__device__ __forceinline__ void cp16(uint32_t s, const void* g) {
    asm volatile("cp.async.cg.shared.global [%0], [%1], 16;" :: "r"(s), "l"(g) : "memory");
}
#define CP_COMMIT() asm volatile("cp.async.commit_group;" ::: "memory")
#define CP_WAIT1()  asm volatile("cp.async.wait_group 1;" ::: "memory")

__device__ __forceinline__ void ldm4(uint32_t* r, uint32_t a) {
    asm volatile("ldmatrix.sync.aligned.m8n8.x4.shared.b16 {%0,%1,%2,%3}, [%4];"
                 : "=r"(r[0]), "=r"(r[1]), "=r"(r[2]), "=r"(r[3]) : "r"(a));
}
__device__ __forceinline__ void ldm4t(uint32_t* r, uint32_t a) {
    asm volatile("ldmatrix.sync.aligned.m8n8.x4.trans.shared.b16 {%0,%1,%2,%3}, [%4];"
                 : "=r"(r[0]), "=r"(r[1]), "=r"(r[2]), "=r"(r[3]) : "r"(a));
}
__device__ __forceinline__ void mma_bf16(float* d, const uint32_t* a, uint32_t b0, uint32_t b1) {
    asm volatile("mma.sync.aligned.m16n8k16.row.col.f32.bf16.bf16.f32 "
                 "{%0,%1,%2,%3}, {%4,%5,%6,%7}, {%8,%9}, {%0,%1,%2,%3};"
                 : "+f"(d[0]), "+f"(d[1]), "+f"(d[2]), "+f"(d[3])
                 : "r"(a[0]), "r"(a[1]), "r"(a[2]), "r"(a[3]), "r"(b0), "r"(b1));
}
__device__ __forceinline__ void mma_f16(float* d, const uint32_t* a, uint32_t b0, uint32_t b1) {
    asm volatile("mma.sync.aligned.m16n8k16.row.col.f32.f16.f16.f32 "
                 "{%0,%1,%2,%3}, {%4,%5,%6,%7}, {%8,%9}, {%0,%1,%2,%3};"
                 : "+f"(d[0]), "+f"(d[1]), "+f"(d[2]), "+f"(d[3])
                 : "r"(a[0]), "r"(a[1]), "r"(a[2]), "r"(a[3]), "r"(b0), "r"(b1));
}
__device__ __forceinline__ void split_bf16(float x, __nv_bfloat16& hi, __nv_bfloat16& lo) {
    hi = __float2bfloat16(x);
    lo = __float2bfloat16(x - __bfloat162float(hi));
}
__device__ __forceinline__ uint32_t pack2(__nv_bfloat16 lo16, __nv_bfloat16 hi16) {
    return (uint32_t)__bfloat16_as_ushort(lo16) | ((uint32_t)__bfloat16_as_ushort(hi16) << 16);
}
__device__ __forceinline__ void pksplit(float x, float y, uint32_t& hi, uint32_t& lo) {
    __nv_bfloat16 hx, lx, hy, ly;
    split_bf16(x, hx, lx);
    split_bf16(y, hy, ly);
    hi = pack2(hx, hy);
    lo = pack2(lx, ly);
}
// fp16 split-pack (for V)
__device__ __forceinline__ void pksplit_f16(float x, float y, uint32_t& hi, uint32_t& lo) {
    const __half hx = __float2half_rn(x), hy = __float2half_rn(y);
    const __half2 h2 = __halves2half2(hx, hy);
    const __half2 l2 = __floats2half2_rn(x - __half2float(hx), y - __half2float(hy));
    hi = *(const uint32_t*)&h2;
    lo = *(const uint32_t*)&l2;
}
__device__ __forceinline__ uint32_t pkf16(float x, float y) {
    const __half2 h2 = __floats2half2_rn(x, y);
    return *(const uint32_t*)&h2;
}

// ---------------- convert kernels ----------------
__global__ __launch_bounds__(256)
void conv_a3(const float* __restrict__ s0, const float* __restrict__ s1,
             const float* __restrict__ s2)
{
    const int z = blockIdx.z;
    const float* src = (z == 0) ? s0 : (z == 1) ? s1 : s2;
    const size_t i4 = ((size_t)blockIdx.x * 256 + threadIdx.x) * 4;
    float4 v = *(const float4*)(src + i4);
    __nv_bfloat16 h0,l0,h1,l1,h2,l2,h3,l3;
    split_bf16(v.x,h0,l0); split_bf16(v.y,h1,l1); split_bf16(v.z,h2,l2); split_bf16(v.w,h3,l3);
    uint32_t* ph = (uint32_t*)(&g_ahi[z][i4]);
    uint32_t* pl = (uint32_t*)(&g_alo[z][i4]);
    ph[0] = pack2(h0,h1); ph[1] = pack2(h2,h3);
    pl[0] = pack2(l0,l1); pl[1] = pack2(l2,l3);
}

// weights: W [k][n] fp32 -> transposed bf16 hi/lo [n][k]; blockIdx.z = which
__global__ __launch_bounds__(256)
void conv_w(const float* __restrict__ w0, const float* __restrict__ w1,
            const float* __restrict__ w2, const float* __restrict__ w3)
{
    const int z = blockIdx.z;
    const float* W = (z == 0) ? w0 : (z == 1) ? w1 : (z == 2) ? w2 : w3;
    __shared__ float tile[32][33];
    const int tx = threadIdx.x & 31;
    const int ty = threadIdx.x >> 5;
    const int kx = blockIdx.x * 32;
    const int nx = blockIdx.y * 32;
#pragma unroll
    for (int i = 0; i < 4; i++)
        tile[ty + 8*i][tx] = W[(size_t)(kx + ty + 8*i) * DM_ + nx + tx];
    __syncthreads();
#pragma unroll
    for (int i = 0; i < 4; i++) {
        const float x = tile[tx][ty + 8*i];
        __nv_bfloat16 h, l;
        split_bf16(x, h, l);
        const size_t o = (size_t)(nx + ty + 8*i) * DM_ + kx + tx;
        g_whi[z][o] = h;
        g_wlo[z][o] = l;
    }
}

// ---------------------------------------------------------------------------
// mma.sync bf16-split GEMM. CTA tile 128(m) x 256(n), 8 warps 2x4, warp tile
// 64x64. K-chunk 32, 3-stage cp.async ring. Passes: AhBh + AlBh + AhBl.
// MODE 0: a_slot = blockIdx.z (QKV fused); Q/K -> bf16 split, V -> fp16 split.
// MODE 1: row-major fp32 to C.
// ---------------------------------------------------------------------------
#define SSTR  80
#define ATILE (128 * SSTR)
#define BTILE (256 * SSTR)
#define STG   (2 * ATILE + 2 * BTILE)
#define GEMM_SMEM (3 * STG)                // 184320

template<int MODE>
__global__ __launch_bounds__(256)
void gemm_mma(int a_slot_in, int w_slot_in, float* __restrict__ C)
{
    extern __shared__ char smem[];
    const uint32_t sb = smem_u32(smem);
    const int tid  = threadIdx.x;
    const int lane = tid & 31, wid = tid >> 5;
    const int wm = wid >> 2, wn = wid & 3;
    const int m0 = blockIdx.y * 128, n0 = blockIdx.x * 256;
    const int a_slot = (MODE == 0) ? (int)blockIdx.z : a_slot_in;
    const int w_slot = (MODE == 0) ? (int)blockIdx.z : w_slot_in;

    const __nv_bfloat16* __restrict__ Ahp = g_ahi[a_slot] + (size_t)m0 * DM_;
    const __nv_bfloat16* __restrict__ Alp = g_alo[a_slot] + (size_t)m0 * DM_;
    const __nv_bfloat16* __restrict__ Bhp = g_whi[w_slot] + (size_t)n0 * DM_;
    const __nv_bfloat16* __restrict__ Blp = g_wlo[w_slot] + (size_t)n0 * DM_;

    float acc[4][8][4];
#pragma unroll
    for (int i = 0; i < 4; i++)
#pragma unroll
        for (int j = 0; j < 8; j++)
#pragma unroll
            for (int t = 0; t < 4; t++) acc[i][j][t] = 0.f;

    const int rr = lane & 7, q = lane >> 3;
    const uint32_t a_base = (uint32_t)((wm*64 + rr + (q & 1)*8) * SSTR + (q >> 1)*16);
    const uint32_t b_base = (uint32_t)((wn*64 + (q >> 1)*8 + rr) * SSTR + (q & 1)*16);

    auto load_chunk = [&](int c, int buf) {
        const int k0 = c * 32;
        const uint32_t st = sb + (uint32_t)buf * STG;
#pragma unroll
        for (int i = 0; i < 6; i++) {
            const int e = tid + i * 256;
            const int row = e >> 2, seg = e & 3;
            if (row < 128) {
                const size_t go = (size_t)row * DM_ + k0 + seg * 8;
                const uint32_t so = (uint32_t)(row * SSTR + seg * 16);
                cp16(st + 0*ATILE + so, Ahp + go);
                cp16(st + 1*ATILE + so, Alp + go);
            } else {
                const int r = row - 128;
                const size_t go = (size_t)r * DM_ + k0 + seg * 8;
                const uint32_t so = (uint32_t)(r * SSTR + seg * 16);
                cp16(st + 2*ATILE + so, Bhp + go);
                cp16(st + 2*ATILE + BTILE + so, Blp + go);
            }
        }
    };

    load_chunk(0, 0); CP_COMMIT();
    load_chunk(1, 1); CP_COMMIT();

    for (int c = 0; c < DM_ / 32; c++) {
        CP_WAIT1();
        __syncthreads();

        const uint32_t st = sb + (uint32_t)(c % 3) * STG;
        const uint32_t Ah_s = st, Al_s = st + ATILE;
        const uint32_t Bh_s = st + 2*ATILE, Bl_s = st + 2*ATILE + BTILE;

#pragma unroll
        for (int s = 0; s < 2; s++) {
            const uint32_t ko = (uint32_t)s * 32;
            uint32_t ah[4][4], al[4][4], bb[4];
#pragma unroll
            for (int f = 0; f < 4; f++) {
                ldm4(ah[f], Ah_s + a_base + (uint32_t)f*16*SSTR + ko);
                ldm4(al[f], Al_s + a_base + (uint32_t)f*16*SSTR + ko);
            }
#pragma unroll
            for (int jn = 0; jn < 4; jn++) {
                const uint32_t off = b_base + (uint32_t)jn*16*SSTR + ko;
                ldm4(bb, Bh_s + off);
#pragma unroll
                for (int f = 0; f < 4; f++) {
                    mma_bf16(acc[f][2*jn],   ah[f], bb[0], bb[1]);
                    mma_bf16(acc[f][2*jn+1], ah[f], bb[2], bb[3]);
                    mma_bf16(acc[f][2*jn],   al[f], bb[0], bb[1]);
                    mma_bf16(acc[f][2*jn+1], al[f], bb[2], bb[3]);
                }
                ldm4(bb, Bl_s + off);
#pragma unroll
                for (int f = 0; f < 4; f++) {
                    mma_bf16(acc[f][2*jn],   ah[f], bb[0], bb[1]);
                    mma_bf16(acc[f][2*jn+1], ah[f], bb[2], bb[3]);
                }
            }
        }

        __syncthreads();
        if (c + 2 < DM_ / 32) load_chunk(c + 2, (c + 2) % 3);
        CP_COMMIT();
    }

    const int r_in = lane >> 2;
    const int c_in = (lane & 3) * 2;
    const float sc = (MODE == 0 && a_slot == 0) ? 0.125f : 1.0f;
#pragma unroll
    for (int i = 0; i < 4; i++) {
        const int mb = m0 + wm*64 + i*16 + r_in;
#pragma unroll
        for (int j = 0; j < 8; j++) {
            const int col = n0 + wn*64 + j*8 + c_in;
            if (MODE == 1) {
                *(float2*)(C + (size_t)mb * DM_ + col)       = make_float2(acc[i][j][0], acc[i][j][1]);
                *(float2*)(C + (size_t)(mb + 8) * DM_ + col) = make_float2(acc[i][j][2], acc[i][j][3]);
            } else {
                const int h = col >> 6, d = col & 63;
                uint32_t phi, plo;
#pragma unroll
                for (int half = 0; half < 2; half++) {
                    const int m2 = mb + half * 8;
                    const int bi = m2 >> 11, si = m2 & (S_ - 1);
                    const size_t off = (((size_t)(bi*NH_ + h))*S_ + si)*DK_ + d;
                    if (a_slot == 2) {       // V: fp16 split
                        pksplit_f16(acc[i][j][2*half], acc[i][j][2*half+1], phi, plo);
                        *(uint32_t*)((__half*)g_vhi + off) = phi;
                        *(uint32_t*)((__half*)g_vlo + off) = plo;
                    } else {                 // Q/K: bf16 split
                        __nv_bfloat16* hb = (a_slot == 0) ? g_qhi : g_khi;
                        __nv_bfloat16* lb = (a_slot == 0) ? g_qlo : g_klo;
                        pksplit(acc[i][j][2*half] * sc, acc[i][j][2*half+1] * sc, phi, plo);
                        *(uint32_t*)(hb + off) = phi;
                        *(uint32_t*)(lb + off) = plo;
                    }
                }
            }
        }
    }
}

// ---------------------------------------------------------------------------
// mma.sync split flash attention, causal. CTA = 128 q-rows of one (b,h),
// 4 warps x 32-row strips. KV tiles 64 rows, double-buffered cp.async.
// QK: bf16 3-pass (QhKh + QlKh + QhKl). PV: fp16 2-pass (P*Vh + P*Vl),
// P single fp16 (err 2^-12, fits budget) -> fewer MMAs, no P split, ~32 fewer
// regs (kills the R9 spills).
// ---------------------------------------------------------------------------
#define ASTR 144
#define QTILE (128 * ASTR)
#define KVTILE (64 * ASTR)
#define SQH 0
#define SQL QTILE
#define SKV (2 * QTILE)
#define KVSTAGE (4 * KVTILE)
#define ATTN_SMEM (2 * QTILE + 2 * KVSTAGE)   // 110592

__global__ __launch_bounds__(128, 2)
void attn_mma()
{
    extern __shared__ char smem[];
    const uint32_t sb = smem_u32(smem);
    const int tid = threadIdx.x, lane = tid & 31, w = tid >> 5;   // w: 0..3
    const int qt = (S_ / 128 - 1) - blockIdx.x;   // heavy tiles first
    const int bh = blockIdx.y;
    const int q0 = qt * 128;
    const int iters = (q0 + 128) / 64;

    const __nv_bfloat16* __restrict__ Qh = g_qhi + ((size_t)bh * S_ + q0) * DK_;
    const __nv_bfloat16* __restrict__ Ql = g_qlo + ((size_t)bh * S_ + q0) * DK_;
    const __nv_bfloat16* __restrict__ Kh = g_khi + (size_t)bh * S_ * DK_;
    const __nv_bfloat16* __restrict__ Kl = g_klo + (size_t)bh * S_ * DK_;
    const __half*        __restrict__ Vh = g_vhi + (size_t)bh * S_ * DK_;
    const __half*        __restrict__ Vl = g_vlo + (size_t)bh * S_ * DK_;

    auto ldkv = [&](int c, int buf) {
        const int j0 = c * 64;
        const uint32_t kb = sb + SKV + (uint32_t)buf * KVSTAGE;
#pragma unroll
        for (int i = 0; i < 4; i++) {
            const int e = tid + i * 128;              // 0..511
            const int r = e >> 3, sg = e & 7;
            const size_t go = (size_t)(j0 + r) * DK_ + sg * 8;
            const uint32_t so = (uint32_t)(r * ASTR + sg * 16);
            cp16(kb + 0*KVTILE + so, Kh + go);
            cp16(kb + 1*KVTILE + so, Kl + go);
            cp16(kb + 2*KVTILE + so, Vh + go);
            cp16(kb + 3*KVTILE + so, Vl + go);
        }
    };

#pragma unroll
    for (int i = 0; i < 8; i++) {
        const int e = tid + i * 128;                  // 0..1023
        const int r = e >> 3, sg = e & 7;
        const size_t go = (size_t)r * DK_ + sg * 8;
        const uint32_t so = (uint32_t)(r * ASTR + sg * 16);
        cp16(sb + SQH + so, Qh + go);
        cp16(sb + SQL + so, Ql + go);
    }
    ldkv(0, 0); CP_COMMIT();
    ldkv(1, 1); CP_COMMIT();

    const int rr = lane & 7, qq = lane >> 3;
    const uint32_t qa_base = (uint32_t)((w*32 + rr + (qq & 1)*8) * ASTR + (qq >> 1)*16);
    const uint32_t kb_row = (uint32_t)(((qq >> 1)*8 + rr) * ASTR + (qq & 1)*16);
    const uint32_t vb_row = (uint32_t)(((qq & 1)*8 + rr) * ASTR + (qq >> 1)*16);

    uint32_t qh[2][4][4], ql[2][4][4];                // f = m16-frag (rows +0, +16)
    float ctx[2][8][4];
#pragma unroll
    for (int f = 0; f < 2; f++)
#pragma unroll
        for (int j = 0; j < 8; j++)
#pragma unroll
            for (int t = 0; t < 4; t++) ctx[f][j][t] = 0.f;
    float mrow[2][2] = {{-1e30f,-1e30f},{-1e30f,-1e30f}};
    float lrow[2][2] = {{0.f,0.f},{0.f,0.f}};

    const int rbase = q0 + w*32 + (lane >> 2);

    for (int c = 0; c < iters; c++) {
        CP_WAIT1();
        __syncthreads();
        if (c == 0) {
#pragma unroll
            for (int f = 0; f < 2; f++)
#pragma unroll
                for (int ks = 0; ks < 4; ks++) {
                    ldm4(qh[f][ks], sb + SQH + qa_base + (uint32_t)f*16*ASTR + ks*32);
                    ldm4(ql[f][ks], sb + SQL + qa_base + (uint32_t)f*16*ASTR + ks*32);
                }
        }
        const uint32_t kb = sb + SKV + (uint32_t)(c & 1) * KVSTAGE;

        // ---- S = Q K^T (3-pass bf16 split) ----
        float s[2][8][4];
#pragma unroll
        for (int f = 0; f < 2; f++)
#pragma unroll
            for (int j = 0; j < 8; j++)
#pragma unroll
                for (int t = 0; t < 4; t++) s[f][j][t] = 0.f;

#pragma unroll
        for (int ks = 0; ks < 4; ks++) {
#pragma unroll
            for (int jn = 0; jn < 4; jn++) {
                uint32_t kh4[4], kl4[4];
                const uint32_t off = (uint32_t)(jn*16*ASTR) + kb_row + ks*32;
                ldm4(kh4, kb + 0*KVTILE + off);
#pragma unroll
                for (int f = 0; f < 2; f++) {
                    mma_bf16(s[f][2*jn],   qh[f][ks], kh4[0], kh4[1]);
                    mma_bf16(s[f][2*jn+1], qh[f][ks], kh4[2], kh4[3]);
                    mma_bf16(s[f][2*jn],   ql[f][ks], kh4[0], kh4[1]);
                    mma_bf16(s[f][2*jn+1], ql[f][ks], kh4[2], kh4[3]);
                }
                ldm4(kl4, kb + 1*KVTILE + off);
#pragma unroll
                for (int f = 0; f < 2; f++) {
                    mma_bf16(s[f][2*jn],   qh[f][ks], kl4[0], kl4[1]);
                    mma_bf16(s[f][2*jn+1], qh[f][ks], kl4[2], kl4[3]);
                }
            }
        }

        // ---- causal mask ----
        const int j0 = c * 64;
        if (j0 + 63 > rbase) {
#pragma unroll
            for (int f = 0; f < 2; f++) {
                const int r1g = rbase + f*16, r2g = r1g + 8;
#pragma unroll
                for (int j = 0; j < 8; j++) {
                    const int cg = j0 + j*8 + (lane & 3)*2;
                    if (cg     > r1g) s[f][j][0] = -1e30f;
                    if (cg + 1 > r1g) s[f][j][1] = -1e30f;
                    if (cg     > r2g) s[f][j][2] = -1e30f;
                    if (cg + 1 > r2g) s[f][j][3] = -1e30f;
                }
            }
        }

        // ---- online softmax + fp16 P pack (no split) ----
        uint32_t p16[2][4][4];
#pragma unroll
        for (int f = 0; f < 2; f++) {
            float mt1 = s[f][0][0], mt2 = s[f][0][2];
#pragma unroll
            for (int j = 0; j < 8; j++) {
                mt1 = fmaxf(mt1, fmaxf(s[f][j][0], s[f][j][1]));
                mt2 = fmaxf(mt2, fmaxf(s[f][j][2], s[f][j][3]));
            }
            mt1 = fmaxf(mt1, __shfl_xor_sync(0xffffffffu, mt1, 1));
            mt1 = fmaxf(mt1, __shfl_xor_sync(0xffffffffu, mt1, 2));
            mt2 = fmaxf(mt2, __shfl_xor_sync(0xffffffffu, mt2, 1));
            mt2 = fmaxf(mt2, __shfl_xor_sync(0xffffffffu, mt2, 2));
            const float mn1 = fmaxf(mrow[f][0], mt1), mn2 = fmaxf(mrow[f][1], mt2);
            const float co1 = __expf(mrow[f][0] - mn1), co2 = __expf(mrow[f][1] - mn2);

            float ps1 = 0.f, ps2 = 0.f;
#pragma unroll
            for (int j = 0; j < 8; j++) {
                s[f][j][0] = __expf(s[f][j][0] - mn1);
                s[f][j][1] = __expf(s[f][j][1] - mn1);
                s[f][j][2] = __expf(s[f][j][2] - mn2);
                s[f][j][3] = __expf(s[f][j][3] - mn2);
                ps1 += s[f][j][0] + s[f][j][1];
                ps2 += s[f][j][2] + s[f][j][3];
            }
            ps1 += __shfl_xor_sync(0xffffffffu, ps1, 1);
            ps1 += __shfl_xor_sync(0xffffffffu, ps1, 2);
            ps2 += __shfl_xor_sync(0xffffffffu, ps2, 1);
            ps2 += __shfl_xor_sync(0xffffffffu, ps2, 2);
            lrow[f][0] = lrow[f][0] * co1 + ps1;  mrow[f][0] = mn1;
            lrow[f][1] = lrow[f][1] * co2 + ps2;  mrow[f][1] = mn2;

#pragma unroll
            for (int j = 0; j < 8; j++) {
                ctx[f][j][0] *= co1; ctx[f][j][1] *= co1;
                ctx[f][j][2] *= co2; ctx[f][j][3] *= co2;
            }

#pragma unroll
            for (int ks = 0; ks < 4; ks++) {
                p16[f][ks][0] = pkf16(s[f][2*ks][0],   s[f][2*ks][1]);
                p16[f][ks][1] = pkf16(s[f][2*ks][2],   s[f][2*ks][3]);
                p16[f][ks][2] = pkf16(s[f][2*ks+1][0], s[f][2*ks+1][1]);
                p16[f][ks][3] = pkf16(s[f][2*ks+1][2], s[f][2*ks+1][3]);
            }
        }

        // ---- ctx += P V (2-pass fp16: P*Vh + P*Vl), V via ldmatrix.trans ----
#pragma unroll
        for (int ks = 0; ks < 4; ks++) {
#pragma unroll
            for (int jd = 0; jd < 4; jd++) {
                uint32_t vh4[4], vl4[4];
                const uint32_t off = (uint32_t)(ks*16*ASTR) + vb_row + jd*32;
                ldm4t(vh4, kb + 2*KVTILE + off);
#pragma unroll
                for (int f = 0; f < 2; f++) {
                    mma_f16(ctx[f][2*jd],   p16[f][ks], vh4[0], vh4[1]);
                    mma_f16(ctx[f][2*jd+1], p16[f][ks], vh4[2], vh4[3]);
                }
                ldm4t(vl4, kb + 3*KVTILE + off);
#pragma unroll
                for (int f = 0; f < 2; f++) {
                    mma_f16(ctx[f][2*jd],   p16[f][ks], vl4[0], vl4[1]);
                    mma_f16(ctx[f][2*jd+1], p16[f][ks], vl4[2], vl4[3]);
                }
            }
        }

        __syncthreads();
        if (c + 2 < iters) ldkv(c + 2, c & 1);
        CP_COMMIT();
    }

    // ---- epilogue: normalize, split, write to GEMM a-slot 3 ----
    const int b = bh >> 4, h = bh & 15;
    __nv_bfloat16* dh = g_ahi[3];
    __nv_bfloat16* dl = g_alo[3];
#pragma unroll
    for (int f = 0; f < 2; f++) {
        const float i1 = 1.0f / lrow[f][0], i2 = 1.0f / lrow[f][1];
        const int r1g = rbase + f*16, r2g = r1g + 8;
#pragma unroll
        for (int j = 0; j < 8; j++) {
            const int col = h*64 + j*8 + (lane & 3)*2;
            uint32_t phi, plo;
            pksplit(ctx[f][j][0] * i1, ctx[f][j][1] * i1, phi, plo);
            const size_t o1 = ((size_t)(b * S_ + r1g)) * DM_ + col;
            *(uint32_t*)(dh + o1) = phi;
            *(uint32_t*)(dl + o1) = plo;
            pksplit(ctx[f][j][2] * i2, ctx[f][j][3] * i2, phi, plo);
            const size_t o2 = ((size_t)(b * S_ + r2g)) * DM_ + col;
            *(uint32_t*)(dh + o2) = phi;
            *(uint32_t*)(dl + o2) = plo;
        }
    }
}

// ---------------------------------------------------------------------------
extern "C" void kernel_launch(void* const* d_in, const int* in_sizes, int n_in,
                              void* d_out, int out_size)
{
    const float* xq = (const float*)d_in[0];
    const float* xk = (const float*)d_in[1];
    const float* xv = (const float*)d_in[2];
    const float* wq = (const float*)d_in[5];
    const float* wk = (const float*)d_in[6];
    const float* wv = (const float*)d_in[7];
    const float* wo = (const float*)d_in[8];
    float* out = (float*)d_out;

    cudaFuncSetAttribute(gemm_mma<0>, cudaFuncAttributeMaxDynamicSharedMemorySize, GEMM_SMEM);
    cudaFuncSetAttribute(gemm_mma<1>, cudaFuncAttributeMaxDynamicSharedMemorySize, GEMM_SMEM);
    cudaFuncSetAttribute(attn_mma,    cudaFuncAttributeMaxDynamicSharedMemorySize, ATTN_SMEM);

    conv_w<<<dim3(DM_ / 32, DM_ / 32, 4), 256>>>(wq, wk, wv, wo);
    conv_a3<<<dim3((M_TOT * DM_) / (256 * 4), 1, 3), 256>>>(xq, xk, xv);

    // fused QKV projections (blockIdx.z = slot)
    gemm_mma<0><<<dim3(DM_ / 256, M_TOT / 128, 3), 256, GEMM_SMEM>>>(0, 0, nullptr);

    attn_mma<<<dim3(S_ / 128, BH_), 128, ATTN_SMEM>>>();

    gemm_mma<1><<<dim3(DM_ / 256, M_TOT / 128), 256, GEMM_SMEM>>>(3, 3, out);
}

// round 15
// speedup vs baseline: 3.7634x; 1.0563x over previous
#include <cuda_runtime.h>
#include <cuda_bf16.h>
#include <cuda_fp16.h>
#include <cstdint>

#define B_   2
#define S_   2048
#define DM_  1024
#define NH_  16
#define DK_  64
#define BH_  (B_*NH_)
#define M_TOT 4096   // B_*S_

// ---------------- device scratch ----------------
// bf16 hi/lo split GEMM inputs. a slots: 0=xq 1=xk 2=xv 3=ctx ; w slots 0..3 ([n][k])
__device__ __nv_bfloat16 g_ahi[4][(size_t)M_TOT * DM_];
__device__ __nv_bfloat16 g_alo[4][(size_t)M_TOT * DM_];
__device__ __nv_bfloat16 g_whi[4][(size_t)DM_ * DM_];
__device__ __nv_bfloat16 g_wlo[4][(size_t)DM_ * DM_];
// split Q/K in bf16 [b,h,s,d] (Q pre-scaled by log2e/8); V single fp16
__device__ __nv_bfloat16 g_qhi[(size_t)BH_ * S_ * DK_];
__device__ __nv_bfloat16 g_qlo[(size_t)BH_ * S_ * DK_];
__device__ __nv_bfloat16 g_khi[(size_t)BH_ * S_ * DK_];
__device__ __nv_bfloat16 g_klo[(size_t)BH_ * S_ * DK_];
__device__ __half        g_v16[(size_t)BH_ * S_ * DK_];

// ---------------- helpers (baseline PTX, sm_80-level: safe on compute_103) ---
__device__ __forceinline__ uint32_t smem_u32(const void* p) {
    uint32_t a;
    asm("{ .reg .u64 t; cvta.to.shared.u64 t, %1; cvt.u32.u64 %0, t; }" : "=r"(a) : "l"(p));
    return a;
}
__device__ __forceinline__ void cp16(uint32_t s, const void* g) {
    asm volatile("cp.async.cg.shared.global [%0], [%1], 16;" :: "r"(s), "l"(g) : "memory");
}
#define CP_COMMIT() asm volatile("cp.async.commit_group;" ::: "memory")
#define CP_WAIT1()  asm volatile("cp.async.wait_group 1;" ::: "memory")

__device__ __forceinline__ void ldm4(uint32_t* r, uint32_t a) {
    asm volatile("ldmatrix.sync.aligned.m8n8.x4.shared.b16 {%0,%1,%2,%3}, [%4];"
                 : "=r"(r[0]), "=r"(r[1]), "=r"(r[2]), "=r"(r[3]) : "r"(a));
}
__device__ __forceinline__ void ldm4t(uint32_t* r, uint32_t a) {
    asm volatile("ldmatrix.sync.aligned.m8n8.x4.trans.shared.b16 {%0,%1,%2,%3}, [%4];"
                 : "=r"(r[0]), "=r"(r[1]), "=r"(r[2]), "=r"(r[3]) : "r"(a));
}
__device__ __forceinline__ void mma_bf16(float* d, const uint32_t* a, uint32_t b0, uint32_t b1) {
    asm volatile("mma.sync.aligned.m16n8k16.row.col.f32.bf16.bf16.f32 "
                 "{%0,%1,%2,%3}, {%4,%5,%6,%7}, {%8,%9}, {%0,%1,%2,%3};"
                 : "+f"(d[0]), "+f"(d[1]), "+f"(d[2]), "+f"(d[3])
                 : "r"(a[0]), "r"(a[1]), "r"(a[2]), "r"(a[3]), "r"(b0), "r"(b1));
}
__device__ __forceinline__ void mma_f16(float* d, const uint32_t* a, uint32_t b0, uint32_t b1) {
    asm volatile("mma.sync.aligned.m16n8k16.row.col.f32.f16.f16.f32 "
                 "{%0,%1,%2,%3}, {%4,%5,%6,%7}, {%8,%9}, {%0,%1,%2,%3};"
                 : "+f"(d[0]), "+f"(d[1]), "+f"(d[2]), "+f"(d[3])
                 : "r"(a[0]), "r"(a[1]), "r"(a[2]), "r"(a[3]), "r"(b0), "r"(b1));
}
__device__ __forceinline__ void split_bf16(float x, __nv_bfloat16& hi, __nv_bfloat16& lo) {
    hi = __float2bfloat16(x);
    lo = __float2bfloat16(x - __bfloat162float(hi));
}
__device__ __forceinline__ uint32_t pack2(__nv_bfloat16 lo16, __nv_bfloat16 hi16) {
    return (uint32_t)__bfloat16_as_ushort(lo16) | ((uint32_t)__bfloat16_as_ushort(hi16) << 16);
}
__device__ __forceinline__ void pksplit(float x, float y, uint32_t& hi, uint32_t& lo) {
    __nv_bfloat16 hx, lx, hy, ly;
    split_bf16(x, hx, lx);
    split_bf16(y, hy, ly);
    hi = pack2(hx, hy);
    lo = pack2(lx, ly);
}
__device__ __forceinline__ uint32_t pkf16(float x, float y) {
    const __half2 h2 = __floats2half2_rn(x, y);
    return *(const uint32_t*)&h2;
}

// ---------------- convert kernels ----------------
__global__ __launch_bounds__(256)
void conv_a3(const float* __restrict__ s0, const float* __restrict__ s1,
             const float* __restrict__ s2)
{
    const int z = blockIdx.z;
    const float* src = (z == 0) ? s0 : (z == 1) ? s1 : s2;
    const size_t i4 = ((size_t)blockIdx.x * 256 + threadIdx.x) * 4;
    float4 v = *(const float4*)(src + i4);
    __nv_bfloat16 h0,l0,h1,l1,h2,l2,h3,l3;
    split_bf16(v.x,h0,l0); split_bf16(v.y,h1,l1); split_bf16(v.z,h2,l2); split_bf16(v.w,h3,l3);
    uint32_t* ph = (uint32_t*)(&g_ahi[z][i4]);
    uint32_t* pl = (uint32_t*)(&g_alo[z][i4]);
    ph[0] = pack2(h0,h1); ph[1] = pack2(h2,h3);
    pl[0] = pack2(l0,l1); pl[1] = pack2(l2,l3);
}

// weights: W [k][n] fp32 -> transposed bf16 hi/lo [n][k]; blockIdx.z = which
__global__ __launch_bounds__(256)
void conv_w(const float* __restrict__ w0, const float* __restrict__ w1,
            const float* __restrict__ w2, const float* __restrict__ w3)
{
    const int z = blockIdx.z;
    const float* W = (z == 0) ? w0 : (z == 1) ? w1 : (z == 2) ? w2 : w3;
    __shared__ float tile[32][33];
    const int tx = threadIdx.x & 31;
    const int ty = threadIdx.x >> 5;
    const int kx = blockIdx.x * 32;
    const int nx = blockIdx.y * 32;
#pragma unroll
    for (int i = 0; i < 4; i++)
        tile[ty + 8*i][tx] = W[(size_t)(kx + ty + 8*i) * DM_ + nx + tx];
    __syncthreads();
#pragma unroll
    for (int i = 0; i < 4; i++) {
        const float x = tile[tx][ty + 8*i];
        __nv_bfloat16 h, l;
        split_bf16(x, h, l);
        const size_t o = (size_t)(nx + ty + 8*i) * DM_ + kx + tx;
        g_whi[z][o] = h;
        g_wlo[z][o] = l;
    }
}

// ---------------------------------------------------------------------------
// mma.sync bf16-split GEMM. CTA tile 128(m) x 256(n), 8 warps 2x4, warp tile
// 64x64. K-chunk 32, 3-stage cp.async ring. Passes: AhBh + AlBh + AhBl.
// MODE 0: a_slot = blockIdx.z (QKV fused); Q/K -> bf16 split (Q scaled by
//         log2e/8 for exp2 softmax), V -> single fp16.
// MODE 1: row-major fp32 to C.
// ---------------------------------------------------------------------------
#define SSTR  80
#define ATILE (128 * SSTR)
#define BTILE (256 * SSTR)
#define STG   (2 * ATILE + 2 * BTILE)
#define GEMM_SMEM (3 * STG)                // 184320

template<int MODE>
__global__ __launch_bounds__(256)
void gemm_mma(int a_slot_in, int w_slot_in, float* __restrict__ C)
{
    extern __shared__ char smem[];
    const uint32_t sb = smem_u32(smem);
    const int tid  = threadIdx.x;
    const int lane = tid & 31, wid = tid >> 5;
    const int wm = wid >> 2, wn = wid & 3;
    const int m0 = blockIdx.y * 128, n0 = blockIdx.x * 256;
    const int a_slot = (MODE == 0) ? (int)blockIdx.z : a_slot_in;
    const int w_slot = (MODE == 0) ? (int)blockIdx.z : w_slot_in;

    const __nv_bfloat16* __restrict__ Ahp = g_ahi[a_slot] + (size_t)m0 * DM_;
    const __nv_bfloat16* __restrict__ Alp = g_alo[a_slot] + (size_t)m0 * DM_;
    const __nv_bfloat16* __restrict__ Bhp = g_whi[w_slot] + (size_t)n0 * DM_;
    const __nv_bfloat16* __restrict__ Blp = g_wlo[w_slot] + (size_t)n0 * DM_;

    float acc[4][8][4];
#pragma unroll
    for (int i = 0; i < 4; i++)
#pragma unroll
        for (int j = 0; j < 8; j++)
#pragma unroll
            for (int t = 0; t < 4; t++) acc[i][j][t] = 0.f;

    const int rr = lane & 7, q = lane >> 3;
    const uint32_t a_base = (uint32_t)((wm*64 + rr + (q & 1)*8) * SSTR + (q >> 1)*16);
    const uint32_t b_base = (uint32_t)((wn*64 + (q >> 1)*8 + rr) * SSTR + (q & 1)*16);

    auto load_chunk = [&](int c, int buf) {
        const int k0 = c * 32;
        const uint32_t st = sb + (uint32_t)buf * STG;
#pragma unroll
        for (int i = 0; i < 6; i++) {
            const int e = tid + i * 256;
            const int row = e >> 2, seg = e & 3;
            if (row < 128) {
                const size_t go = (size_t)row * DM_ + k0 + seg * 8;
                const uint32_t so = (uint32_t)(row * SSTR + seg * 16);
                cp16(st + 0*ATILE + so, Ahp + go);
                cp16(st + 1*ATILE + so, Alp + go);
            } else {
                const int r = row - 128;
                const size_t go = (size_t)r * DM_ + k0 + seg * 8;
                const uint32_t so = (uint32_t)(r * SSTR + seg * 16);
                cp16(st + 2*ATILE + so, Bhp + go);
                cp16(st + 2*ATILE + BTILE + so, Blp + go);
            }
        }
    };

    load_chunk(0, 0); CP_COMMIT();
    load_chunk(1, 1); CP_COMMIT();

    for (int c = 0; c < DM_ / 32; c++) {
        CP_WAIT1();
        __syncthreads();

        const uint32_t st = sb + (uint32_t)(c % 3) * STG;
        const uint32_t Ah_s = st, Al_s = st + ATILE;
        const uint32_t Bh_s = st + 2*ATILE, Bl_s = st + 2*ATILE + BTILE;

#pragma unroll
        for (int s = 0; s < 2; s++) {
            const uint32_t ko = (uint32_t)s * 32;
            uint32_t ah[4][4], al[4][4], bb[4];
#pragma unroll
            for (int f = 0; f < 4; f++) {
                ldm4(ah[f], Ah_s + a_base + (uint32_t)f*16*SSTR + ko);
                ldm4(al[f], Al_s + a_base + (uint32_t)f*16*SSTR + ko);
            }
#pragma unroll
            for (int jn = 0; jn < 4; jn++) {
                const uint32_t off = b_base + (uint32_t)jn*16*SSTR + ko;
                ldm4(bb, Bh_s + off);
#pragma unroll
                for (int f = 0; f < 4; f++) {
                    mma_bf16(acc[f][2*jn],   ah[f], bb[0], bb[1]);
                    mma_bf16(acc[f][2*jn+1], ah[f], bb[2], bb[3]);
                    mma_bf16(acc[f][2*jn],   al[f], bb[0], bb[1]);
                    mma_bf16(acc[f][2*jn+1], al[f], bb[2], bb[3]);
                }
                ldm4(bb, Bl_s + off);
#pragma unroll
                for (int f = 0; f < 4; f++) {
                    mma_bf16(acc[f][2*jn],   ah[f], bb[0], bb[1]);
                    mma_bf16(acc[f][2*jn+1], ah[f], bb[2], bb[3]);
                }
            }
        }

        __syncthreads();
        if (c + 2 < DM_ / 32) load_chunk(c + 2, (c + 2) % 3);
        CP_COMMIT();
    }

    const int r_in = lane >> 2;
    const int c_in = (lane & 3) * 2;
    // Q pre-scale: 1/sqrt(64) * log2(e)  (softmax done in base 2)
    const float sc = (MODE == 0 && a_slot == 0) ? 0.125f * 1.44269504f : 1.0f;
#pragma unroll
    for (int i = 0; i < 4; i++) {
        const int mb = m0 + wm*64 + i*16 + r_in;
#pragma unroll
        for (int j = 0; j < 8; j++) {
            const int col = n0 + wn*64 + j*8 + c_in;
            if (MODE == 1) {
                *(float2*)(C + (size_t)mb * DM_ + col)       = make_float2(acc[i][j][0], acc[i][j][1]);
                *(float2*)(C + (size_t)(mb + 8) * DM_ + col) = make_float2(acc[i][j][2], acc[i][j][3]);
            } else {
                const int h = col >> 6, d = col & 63;
#pragma unroll
                for (int half = 0; half < 2; half++) {
                    const int m2 = mb + half * 8;
                    const int bi = m2 >> 11, si = m2 & (S_ - 1);
                    const size_t off = (((size_t)(bi*NH_ + h))*S_ + si)*DK_ + d;
                    if (a_slot == 2) {       // V: single fp16
                        *(uint32_t*)((__half*)g_v16 + off) =
                            pkf16(acc[i][j][2*half], acc[i][j][2*half+1]);
                    } else {                 // Q/K: bf16 split
                        __nv_bfloat16* hb = (a_slot == 0) ? g_qhi : g_khi;
                        __nv_bfloat16* lb = (a_slot == 0) ? g_qlo : g_klo;
                        uint32_t phi, plo;
                        pksplit(acc[i][j][2*half] * sc, acc[i][j][2*half+1] * sc, phi, plo);
                        *(uint32_t*)(hb + off) = phi;
                        *(uint32_t*)(lb + off) = plo;
                    }
                }
            }
        }
    }
}

// ---------------------------------------------------------------------------
// mma.sync split flash attention, causal. CTA = 128 q-rows of one (b,h),
// 4 warps x 32-row strips. KV tiles 64 rows, double-buffered cp.async.
// QK: bf16 3-pass (QhKh + QlKh + QhKl), logits pre-scaled by log2e -> exp2.
// PV: single fp16 pass (P fp16, V fp16) -> 160 MMA/warp/iter (was 224).
// ---------------------------------------------------------------------------
#define ASTR 144
#define QTILE (128 * ASTR)
#define KVTILE (64 * ASTR)
#define SQH 0
#define SQL QTILE
#define SKV (2 * QTILE)
#define KVSTAGE (3 * KVTILE)                  // Kh, Kl, V16
#define ATTN_SMEM (2 * QTILE + 2 * KVSTAGE)   // 92160

__global__ __launch_bounds__(128, 2)
void attn_mma()
{
    extern __shared__ char smem[];
    const uint32_t sb = smem_u32(smem);
    const int tid = threadIdx.x, lane = tid & 31, w = tid >> 5;   // w: 0..3
    const int qt = (S_ / 128 - 1) - blockIdx.x;   // heavy tiles first
    const int bh = blockIdx.y;
    const int q0 = qt * 128;
    const int iters = (q0 + 128) / 64;

    const __nv_bfloat16* __restrict__ Qh = g_qhi + ((size_t)bh * S_ + q0) * DK_;
    const __nv_bfloat16* __restrict__ Ql = g_qlo + ((size_t)bh * S_ + q0) * DK_;
    const __nv_bfloat16* __restrict__ Kh = g_khi + (size_t)bh * S_ * DK_;
    const __nv_bfloat16* __restrict__ Kl = g_klo + (size_t)bh * S_ * DK_;
    const __half*        __restrict__ Vp = g_v16 + (size_t)bh * S_ * DK_;

    auto ldkv = [&](int c, int buf) {
        const int j0 = c * 64;
        const uint32_t kb = sb + SKV + (uint32_t)buf * KVSTAGE;
#pragma unroll
        for (int i = 0; i < 4; i++) {
            const int e = tid + i * 128;              // 0..511
            const int r = e >> 3, sg = e & 7;
            const size_t go = (size_t)(j0 + r) * DK_ + sg * 8;
            const uint32_t so = (uint32_t)(r * ASTR + sg * 16);
            cp16(kb + 0*KVTILE + so, Kh + go);
            cp16(kb + 1*KVTILE + so, Kl + go);
            cp16(kb + 2*KVTILE + so, Vp + go);
        }
    };

#pragma unroll
    for (int i = 0; i < 8; i++) {
        const int e = tid + i * 128;                  // 0..1023
        const int r = e >> 3, sg = e & 7;
        const size_t go = (size_t)r * DK_ + sg * 8;
        const uint32_t so = (uint32_t)(r * ASTR + sg * 16);
        cp16(sb + SQH + so, Qh + go);
        cp16(sb + SQL + so, Ql + go);
    }
    ldkv(0, 0); CP_COMMIT();
    ldkv(1, 1); CP_COMMIT();

    const int rr = lane & 7, qq = lane >> 3;
    const uint32_t qa_base = (uint32_t)((w*32 + rr + (qq & 1)*8) * ASTR + (qq >> 1)*16);
    const uint32_t kb_row = (uint32_t)(((qq >> 1)*8 + rr) * ASTR + (qq & 1)*16);
    const uint32_t vb_row = (uint32_t)(((qq & 1)*8 + rr) * ASTR + (qq >> 1)*16);

    uint32_t qh[2][4][4], ql[2][4][4];                // f = m16-frag (rows +0, +16)
    float ctx[2][8][4];
#pragma unroll
    for (int f = 0; f < 2; f++)
#pragma unroll
        for (int j = 0; j < 8; j++)
#pragma unroll
            for (int t = 0; t < 4; t++) ctx[f][j][t] = 0.f;
    float mrow[2][2] = {{-1e30f,-1e30f},{-1e30f,-1e30f}};
    float lrow[2][2] = {{0.f,0.f},{0.f,0.f}};

    const int rbase = q0 + w*32 + (lane >> 2);

    for (int c = 0; c < iters; c++) {
        CP_WAIT1();
        __syncthreads();
        if (c == 0) {
#pragma unroll
            for (int f = 0; f < 2; f++)
#pragma unroll
                for (int ks = 0; ks < 4; ks++) {
                    ldm4(qh[f][ks], sb + SQH + qa_base + (uint32_t)f*16*ASTR + ks*32);
                    ldm4(ql[f][ks], sb + SQL + qa_base + (uint32_t)f*16*ASTR + ks*32);
                }
        }
        const uint32_t kb = sb + SKV + (uint32_t)(c & 1) * KVSTAGE;

        // ---- S = Q K^T (3-pass bf16 split; logits already in log2 units) ----
        float s[2][8][4];
#pragma unroll
        for (int f = 0; f < 2; f++)
#pragma unroll
            for (int j = 0; j < 8; j++)
#pragma unroll
                for (int t = 0; t < 4; t++) s[f][j][t] = 0.f;

#pragma unroll
        for (int ks = 0; ks < 4; ks++) {
#pragma unroll
            for (int jn = 0; jn < 4; jn++) {
                uint32_t kh4[4], kl4[4];
                const uint32_t off = (uint32_t)(jn*16*ASTR) + kb_row + ks*32;
                ldm4(kh4, kb + 0*KVTILE + off);
#pragma unroll
                for (int f = 0; f < 2; f++) {
                    mma_bf16(s[f][2*jn],   qh[f][ks], kh4[0], kh4[1]);
                    mma_bf16(s[f][2*jn+1], qh[f][ks], kh4[2], kh4[3]);
                    mma_bf16(s[f][2*jn],   ql[f][ks], kh4[0], kh4[1]);
                    mma_bf16(s[f][2*jn+1], ql[f][ks], kh4[2], kh4[3]);
                }
                ldm4(kl4, kb + 1*KVTILE + off);
#pragma unroll
                for (int f = 0; f < 2; f++) {
                    mma_bf16(s[f][2*jn],   qh[f][ks], kl4[0], kl4[1]);
                    mma_bf16(s[f][2*jn+1], qh[f][ks], kl4[2], kl4[3]);
                }
            }
        }

        // ---- causal mask ----
        const int j0 = c * 64;
        if (j0 + 63 > rbase) {
#pragma unroll
            for (int f = 0; f < 2; f++) {
                const int r1g = rbase + f*16, r2g = r1g + 8;
#pragma unroll
                for (int j = 0; j < 8; j++) {
                    const int cg = j0 + j*8 + (lane & 3)*2;
                    if (cg     > r1g) s[f][j][0] = -1e30f;
                    if (cg + 1 > r1g) s[f][j][1] = -1e30f;
                    if (cg     > r2g) s[f][j][2] = -1e30f;
                    if (cg + 1 > r2g) s[f][j][3] = -1e30f;
                }
            }
        }

        // ---- online softmax (base-2) + fp16 P pack ----
        uint32_t p16[2][4][4];
#pragma unroll
        for (int f = 0; f < 2; f++) {
            float mt1 = s[f][0][0], mt2 = s[f][0][2];
#pragma unroll
            for (int j = 0; j < 8; j++) {
                mt1 = fmaxf(mt1, fmaxf(s[f][j][0], s[f][j][1]));
                mt2 = fmaxf(mt2, fmaxf(s[f][j][2], s[f][j][3]));
            }
            mt1 = fmaxf(mt1, __shfl_xor_sync(0xffffffffu, mt1, 1));
            mt1 = fmaxf(mt1, __shfl_xor_sync(0xffffffffu, mt1, 2));
            mt2 = fmaxf(mt2, __shfl_xor_sync(0xffffffffu, mt2, 1));
            mt2 = fmaxf(mt2, __shfl_xor_sync(0xffffffffu, mt2, 2));
            const float mn1 = fmaxf(mrow[f][0], mt1), mn2 = fmaxf(mrow[f][1], mt2);
            const float co1 = exp2f(mrow[f][0] - mn1), co2 = exp2f(mrow[f][1] - mn2);

            float ps1 = 0.f, ps2 = 0.f;
#pragma unroll
            for (int j = 0; j < 8; j++) {
                s[f][j][0] = exp2f(s[f][j][0] - mn1);
                s[f][j][1] = exp2f(s[f][j][1] - mn1);
                s[f][j][2] = exp2f(s[f][j][2] - mn2);
                s[f][j][3] = exp2f(s[f][j][3] - mn2);
                ps1 += s[f][j][0] + s[f][j][1];
                ps2 += s[f][j][2] + s[f][j][3];
            }
            ps1 += __shfl_xor_sync(0xffffffffu, ps1, 1);
            ps1 += __shfl_xor_sync(0xffffffffu, ps1, 2);
            ps2 += __shfl_xor_sync(0xffffffffu, ps2, 1);
            ps2 += __shfl_xor_sync(0xffffffffu, ps2, 2);
            lrow[f][0] = lrow[f][0] * co1 + ps1;  mrow[f][0] = mn1;
            lrow[f][1] = lrow[f][1] * co2 + ps2;  mrow[f][1] = mn2;

#pragma unroll
            for (int j = 0; j < 8; j++) {
                ctx[f][j][0] *= co1; ctx[f][j][1] *= co1;
                ctx[f][j][2] *= co2; ctx[f][j][3] *= co2;
            }

#pragma unroll
            for (int ks = 0; ks < 4; ks++) {
                p16[f][ks][0] = pkf16(s[f][2*ks][0],   s[f][2*ks][1]);
                p16[f][ks][1] = pkf16(s[f][2*ks][2],   s[f][2*ks][3]);
                p16[f][ks][2] = pkf16(s[f][2*ks+1][0], s[f][2*ks+1][1]);
                p16[f][ks][3] = pkf16(s[f][2*ks+1][2], s[f][2*ks+1][3]);
            }
        }

        // ---- ctx += P V (single fp16 pass), V via ldmatrix.trans ----
#pragma unroll
        for (int ks = 0; ks < 4; ks++) {
#pragma unroll
            for (int jd = 0; jd < 4; jd++) {
                uint32_t v4[4];
                const uint32_t off = (uint32_t)(ks*16*ASTR) + vb_row + jd*32;
                ldm4t(v4, kb + 2*KVTILE + off);
#pragma unroll
                for (int f = 0; f < 2; f++) {
                    mma_f16(ctx[f][2*jd],   p16[f][ks], v4[0], v4[1]);
                    mma_f16(ctx[f][2*jd+1], p16[f][ks], v4[2], v4[3]);
                }
            }
        }

        __syncthreads();
        if (c + 2 < iters) ldkv(c + 2, c & 1);
        CP_COMMIT();
    }

    // ---- epilogue: normalize, split, write to GEMM a-slot 3 ----
    const int b = bh >> 4, h = bh & 15;
    __nv_bfloat16* dh = g_ahi[3];
    __nv_bfloat16* dl = g_alo[3];
#pragma unroll
    for (int f = 0; f < 2; f++) {
        const float i1 = 1.0f / lrow[f][0], i2 = 1.0f / lrow[f][1];
        const int r1g = rbase + f*16, r2g = r1g + 8;
#pragma unroll
        for (int j = 0; j < 8; j++) {
            const int col = h*64 + j*8 + (lane & 3)*2;
            uint32_t phi, plo;
            pksplit(ctx[f][j][0] * i1, ctx[f][j][1] * i1, phi, plo);
            const size_t o1 = ((size_t)(b * S_ + r1g)) * DM_ + col;
            *(uint32_t*)(dh + o1) = phi;
            *(uint32_t*)(dl + o1) = plo;
            pksplit(ctx[f][j][2] * i2, ctx[f][j][3] * i2, phi, plo);
            const size_t o2 = ((size_t)(b * S_ + r2g)) * DM_ + col;
            *(uint32_t*)(dh + o2) = phi;
            *(uint32_t*)(dl + o2) = plo;
        }
    }
}

// ---------------------------------------------------------------------------
extern "C" void kernel_launch(void* const* d_in, const int* in_sizes, int n_in,
                              void* d_out, int out_size)
{
    const float* xq = (const float*)d_in[0];
    const float* xk = (const float*)d_in[1];
    const float* xv = (const float*)d_in[2];
    const float* wq = (const float*)d_in[5];
    const float* wk = (const float*)d_in[6];
    const float* wv = (const float*)d_in[7];
    const float* wo = (const float*)d_in[8];
    float* out = (float*)d_out;

    cudaFuncSetAttribute(gemm_mma<0>, cudaFuncAttributeMaxDynamicSharedMemorySize, GEMM_SMEM);
    cudaFuncSetAttribute(gemm_mma<1>, cudaFuncAttributeMaxDynamicSharedMemorySize, GEMM_SMEM);
    cudaFuncSetAttribute(attn_mma,    cudaFuncAttributeMaxDynamicSharedMemorySize, ATTN_SMEM);

    conv_w<<<dim3(DM_ / 32, DM_ / 32, 4), 256>>>(wq, wk, wv, wo);
    conv_a3<<<dim3((M_TOT * DM_) / (256 * 4), 1, 3), 256>>>(xq, xk, xv);

    // fused QKV projections (blockIdx.z = slot)
    gemm_mma<0><<<dim3(DM_ / 256, M_TOT / 128, 3), 256, GEMM_SMEM>>>(0, 0, nullptr);

    attn_mma<<<dim3(S_ / 128, BH_), 128, ATTN_SMEM>>>();

    gemm_mma<1><<<dim3(DM_ / 256, M_TOT / 128), 256, GEMM_SMEM>>>(3, 3, out);
}

// round 16
// speedup vs baseline: 4.5849x; 1.2183x over previous
#include <cuda_runtime.h>
#include <cuda_bf16.h>
#include <cuda_fp16.h>
#include <cstdint>

#define B_   2
#define S_   2048
#define DM_  1024
#define NH_  16
#define DK_  64
#define BH_  (B_*NH_)
#define M_TOT 4096   // B_*S_

// ---------------- device scratch ----------------
// GEMM inputs: activations single fp16 (slots 0=xq 1=xk 2=xv 3=ctx),
// weights fp16 hi/lo split, transposed [n][k].
__device__ __half g_a16[4][(size_t)M_TOT * DM_];
__device__ __half g_whi[4][(size_t)DM_ * DM_];
__device__ __half g_wlo[4][(size_t)DM_ * DM_];
// split Q/K in bf16 [b,h,s,d] (Q pre-scaled by log2e/8); V single fp16
__device__ __nv_bfloat16 g_qhi[(size_t)BH_ * S_ * DK_];
__device__ __nv_bfloat16 g_qlo[(size_t)BH_ * S_ * DK_];
__device__ __nv_bfloat16 g_khi[(size_t)BH_ * S_ * DK_];
__device__ __nv_bfloat16 g_klo[(size_t)BH_ * S_ * DK_];
__device__ __half        g_v16[(size_t)BH_ * S_ * DK_];

// ---------------- helpers (baseline PTX, sm_80-level: safe on compute_103) ---
__device__ __forceinline__ uint32_t smem_u32(const void* p) {
    uint32_t a;
    asm("{ .reg .u64 t; cvta.to.shared.u64 t, %1; cvt.u32.u64 %0, t; }" : "=r"(a) : "l"(p));
    return a;
}
__device__ __forceinline__ void cp16(uint32_t s, const void* g) {
    asm volatile("cp.async.cg.shared.global [%0], [%1], 16;" :: "r"(s), "l"(g) : "memory");
}
#define CP_COMMIT() asm volatile("cp.async.commit_group;" ::: "memory")
#define CP_WAIT1()  asm volatile("cp.async.wait_group 1;" ::: "memory")

__device__ __forceinline__ void ldm4(uint32_t* r, uint32_t a) {
    asm volatile("ldmatrix.sync.aligned.m8n8.x4.shared.b16 {%0,%1,%2,%3}, [%4];"
                 : "=r"(r[0]), "=r"(r[1]), "=r"(r[2]), "=r"(r[3]) : "r"(a));
}
__device__ __forceinline__ void ldm4t(uint32_t* r, uint32_t a) {
    asm volatile("ldmatrix.sync.aligned.m8n8.x4.trans.shared.b16 {%0,%1,%2,%3}, [%4];"
                 : "=r"(r[0]), "=r"(r[1]), "=r"(r[2]), "=r"(r[3]) : "r"(a));
}
__device__ __forceinline__ void mma_bf16(float* d, const uint32_t* a, uint32_t b0, uint32_t b1) {
    asm volatile("mma.sync.aligned.m16n8k16.row.col.f32.bf16.bf16.f32 "
                 "{%0,%1,%2,%3}, {%4,%5,%6,%7}, {%8,%9}, {%0,%1,%2,%3};"
                 : "+f"(d[0]), "+f"(d[1]), "+f"(d[2]), "+f"(d[3])
                 : "r"(a[0]), "r"(a[1]), "r"(a[2]), "r"(a[3]), "r"(b0), "r"(b1));
}
__device__ __forceinline__ void mma_f16(float* d, const uint32_t* a, uint32_t b0, uint32_t b1) {
    asm volatile("mma.sync.aligned.m16n8k16.row.col.f32.f16.f16.f32 "
                 "{%0,%1,%2,%3}, {%4,%5,%6,%7}, {%8,%9}, {%0,%1,%2,%3};"
                 : "+f"(d[0]), "+f"(d[1]), "+f"(d[2]), "+f"(d[3])
                 : "r"(a[0]), "r"(a[1]), "r"(a[2]), "r"(a[3]), "r"(b0), "r"(b1));
}
__device__ __forceinline__ void split_bf16(float x, __nv_bfloat16& hi, __nv_bfloat16& lo) {
    hi = __float2bfloat16(x);
    lo = __float2bfloat16(x - __bfloat162float(hi));
}
__device__ __forceinline__ uint32_t pack2(__nv_bfloat16 lo16, __nv_bfloat16 hi16) {
    return (uint32_t)__bfloat16_as_ushort(lo16) | ((uint32_t)__bfloat16_as_ushort(hi16) << 16);
}
__device__ __forceinline__ void pksplit(float x, float y, uint32_t& hi, uint32_t& lo) {
    __nv_bfloat16 hx, lx, hy, ly;
    split_bf16(x, hx, lx);
    split_bf16(y, hy, ly);
    hi = pack2(hx, hy);
    lo = pack2(lx, ly);
}
__device__ __forceinline__ uint32_t pkf16(float x, float y) {
    const __half2 h2 = __floats2half2_rn(x, y);
    return *(const uint32_t*)&h2;
}

// ---------------- convert kernels ----------------
// activations fp32 -> single fp16, slots 0..2
__global__ __launch_bounds__(256)
void conv_a3(const float* __restrict__ s0, const float* __restrict__ s1,
             const float* __restrict__ s2)
{
    const int z = blockIdx.z;
    const float* src = (z == 0) ? s0 : (z == 1) ? s1 : s2;
    const size_t i4 = ((size_t)blockIdx.x * 256 + threadIdx.x) * 4;
    float4 v = *(const float4*)(src + i4);
    uint32_t* p = (uint32_t*)(&g_a16[z][i4]);
    p[0] = pkf16(v.x, v.y);
    p[1] = pkf16(v.z, v.w);
}

// weights: W [k][n] fp32 -> transposed fp16 hi/lo [n][k]; blockIdx.z = which
__global__ __launch_bounds__(256)
void conv_w(const float* __restrict__ w0, const float* __restrict__ w1,
            const float* __restrict__ w2, const float* __restrict__ w3)
{
    const int z = blockIdx.z;
    const float* W = (z == 0) ? w0 : (z == 1) ? w1 : (z == 2) ? w2 : w3;
    __shared__ float tile[32][33];
    const int tx = threadIdx.x & 31;
    const int ty = threadIdx.x >> 5;
    const int kx = blockIdx.x * 32;
    const int nx = blockIdx.y * 32;
#pragma unroll
    for (int i = 0; i < 4; i++)
        tile[ty + 8*i][tx] = W[(size_t)(kx + ty + 8*i) * DM_ + nx + tx];
    __syncthreads();
#pragma unroll
    for (int i = 0; i < 4; i++) {
        const float x = tile[tx][ty + 8*i];
        const __half h = __float2half_rn(x);
        const __half l = __float2half_rn(x - __half2float(h));
        const size_t o = (size_t)(nx + ty + 8*i) * DM_ + kx + tx;
        g_whi[z][o] = h;
        g_wlo[z][o] = l;
    }
}

// ---------------------------------------------------------------------------
// mma.sync fp16 2-pass GEMM: A single fp16, W fp16 hi/lo (A*Wh + A*Wl).
// CTA tile 128(m) x 256(n), 8 warps 2x4, warp tile 64x64. K-chunk 32,
// 3-stage cp.async ring.
// MODE 0: a_slot = blockIdx.z (QKV fused); Q/K -> bf16 split (Q scaled by
//         log2e/8 for exp2 softmax), V -> single fp16.
// MODE 1: row-major fp32 to C.
// ---------------------------------------------------------------------------
#define SSTR  80
#define ATILE (128 * SSTR)                 // 10240
#define BTILE (256 * SSTR)                 // 20480
#define STG   (ATILE + 2 * BTILE)          // 51200
#define GEMM_SMEM (3 * STG)                // 153600

template<int MODE>
__global__ __launch_bounds__(256)
void gemm_mma(int a_slot_in, int w_slot_in, float* __restrict__ C)
{
    extern __shared__ char smem[];
    const uint32_t sb = smem_u32(smem);
    const int tid  = threadIdx.x;
    const int lane = tid & 31, wid = tid >> 5;
    const int wm = wid >> 2, wn = wid & 3;
    const int m0 = blockIdx.y * 128, n0 = blockIdx.x * 256;
    const int a_slot = (MODE == 0) ? (int)blockIdx.z : a_slot_in;
    const int w_slot = (MODE == 0) ? (int)blockIdx.z : w_slot_in;

    const __half* __restrict__ Ap  = g_a16[a_slot] + (size_t)m0 * DM_;
    const __half* __restrict__ Bhp = g_whi[w_slot] + (size_t)n0 * DM_;
    const __half* __restrict__ Blp = g_wlo[w_slot] + (size_t)n0 * DM_;

    float acc[4][8][4];
#pragma unroll
    for (int i = 0; i < 4; i++)
#pragma unroll
        for (int j = 0; j < 8; j++)
#pragma unroll
            for (int t = 0; t < 4; t++) acc[i][j][t] = 0.f;

    const int rr = lane & 7, q = lane >> 3;
    const uint32_t a_base = (uint32_t)((wm*64 + rr + (q & 1)*8) * SSTR + (q >> 1)*16);
    const uint32_t b_base = (uint32_t)((wn*64 + (q >> 1)*8 + rr) * SSTR + (q & 1)*16);

    auto load_chunk = [&](int c, int buf) {
        const int k0 = c * 32;
        const uint32_t st = sb + (uint32_t)buf * STG;
#pragma unroll
        for (int i = 0; i < 6; i++) {
            const int e = tid + i * 256;              // 0..1535
            const int row = e >> 2, seg = e & 3;
            if (row < 128) {                          // A rows (single)
                const size_t go = (size_t)row * DM_ + k0 + seg * 8;
                const uint32_t so = (uint32_t)(row * SSTR + seg * 16);
                cp16(st + so, Ap + go);
            } else {                                  // B rows (hi + lo)
                const int r = row - 128;
                const size_t go = (size_t)r * DM_ + k0 + seg * 8;
                const uint32_t so = (uint32_t)(r * SSTR + seg * 16);
                cp16(st + ATILE + so, Bhp + go);
                cp16(st + ATILE + BTILE + so, Blp + go);
            }
        }
    };

    load_chunk(0, 0); CP_COMMIT();
    load_chunk(1, 1); CP_COMMIT();

    for (int c = 0; c < DM_ / 32; c++) {
        CP_WAIT1();
        __syncthreads();

        const uint32_t st = sb + (uint32_t)(c % 3) * STG;
        const uint32_t A_s = st, Bh_s = st + ATILE, Bl_s = st + ATILE + BTILE;

#pragma unroll
        for (int s = 0; s < 2; s++) {
            const uint32_t ko = (uint32_t)s * 32;
            uint32_t a[4][4], bb[4];
#pragma unroll
            for (int f = 0; f < 4; f++)
                ldm4(a[f], A_s + a_base + (uint32_t)f*16*SSTR + ko);
#pragma unroll
            for (int jn = 0; jn < 4; jn++) {
                const uint32_t off = b_base + (uint32_t)jn*16*SSTR + ko;
                ldm4(bb, Bh_s + off);
#pragma unroll
                for (int f = 0; f < 4; f++) {
                    mma_f16(acc[f][2*jn],   a[f], bb[0], bb[1]);
                    mma_f16(acc[f][2*jn+1], a[f], bb[2], bb[3]);
                }
                ldm4(bb, Bl_s + off);
#pragma unroll
                for (int f = 0; f < 4; f++) {
                    mma_f16(acc[f][2*jn],   a[f], bb[0], bb[1]);
                    mma_f16(acc[f][2*jn+1], a[f], bb[2], bb[3]);
                }
            }
        }

        __syncthreads();
        if (c + 2 < DM_ / 32) load_chunk(c + 2, (c + 2) % 3);
        CP_COMMIT();
    }

    const int r_in = lane >> 2;
    const int c_in = (lane & 3) * 2;
    // Q pre-scale: 1/sqrt(64) * log2(e)  (softmax done in base 2)
    const float sc = (MODE == 0 && a_slot == 0) ? 0.125f * 1.44269504f : 1.0f;
#pragma unroll
    for (int i = 0; i < 4; i++) {
        const int mb = m0 + wm*64 + i*16 + r_in;
#pragma unroll
        for (int j = 0; j < 8; j++) {
            const int col = n0 + wn*64 + j*8 + c_in;
            if (MODE == 1) {
                *(float2*)(C + (size_t)mb * DM_ + col)       = make_float2(acc[i][j][0], acc[i][j][1]);
                *(float2*)(C + (size_t)(mb + 8) * DM_ + col) = make_float2(acc[i][j][2], acc[i][j][3]);
            } else {
                const int h = col >> 6, d = col & 63;
#pragma unroll
                for (int half = 0; half < 2; half++) {
                    const int m2 = mb + half * 8;
                    const int bi = m2 >> 11, si = m2 & (S_ - 1);
                    const size_t off = (((size_t)(bi*NH_ + h))*S_ + si)*DK_ + d;
                    if (a_slot == 2) {       // V: single fp16
                        *(uint32_t*)((__half*)g_v16 + off) =
                            pkf16(acc[i][j][2*half], acc[i][j][2*half+1]);
                    } else {                 // Q/K: bf16 split
                        __nv_bfloat16* hb = (a_slot == 0) ? g_qhi : g_khi;
                        __nv_bfloat16* lb = (a_slot == 0) ? g_qlo : g_klo;
                        uint32_t phi, plo;
                        pksplit(acc[i][j][2*half] * sc, acc[i][j][2*half+1] * sc, phi, plo);
                        *(uint32_t*)(hb + off) = phi;
                        *(uint32_t*)(lb + off) = plo;
                    }
                }
            }
        }
    }
}

// ---------------------------------------------------------------------------
// mma.sync split flash attention, causal. CTA = 128 q-rows of one (b,h),
// 4 warps x 32-row strips. KV tiles 64 rows, double-buffered cp.async.
// QK: bf16 3-pass (QhKh + QlKh + QhKl), logits pre-scaled by log2e -> exp2.
// PV: single fp16 pass. ctx written single fp16 straight into GEMM slot 3.
// ---------------------------------------------------------------------------
#define ASTR 144
#define QTILE (128 * ASTR)
#define KVTILE (64 * ASTR)
#define SQH 0
#define SQL QTILE
#define SKV (2 * QTILE)
#define KVSTAGE (3 * KVTILE)                  // Kh, Kl, V16
#define ATTN_SMEM (2 * QTILE + 2 * KVSTAGE)   // 92160

__global__ __launch_bounds__(128, 2)
void attn_mma()
{
    extern __shared__ char smem[];
    const uint32_t sb = smem_u32(smem);
    const int tid = threadIdx.x, lane = tid & 31, w = tid >> 5;   // w: 0..3
    const int qt = (S_ / 128 - 1) - blockIdx.x;   // heavy tiles first
    const int bh = blockIdx.y;
    const int q0 = qt * 128;
    const int iters = (q0 + 128) / 64;

    const __nv_bfloat16* __restrict__ Qh = g_qhi + ((size_t)bh * S_ + q0) * DK_;
    const __nv_bfloat16* __restrict__ Ql = g_qlo + ((size_t)bh * S_ + q0) * DK_;
    const __nv_bfloat16* __restrict__ Kh = g_khi + (size_t)bh * S_ * DK_;
    const __nv_bfloat16* __restrict__ Kl = g_klo + (size_t)bh * S_ * DK_;
    const __half*        __restrict__ Vp = g_v16 + (size_t)bh * S_ * DK_;

    auto ldkv = [&](int c, int buf) {
        const int j0 = c * 64;
        const uint32_t kb = sb + SKV + (uint32_t)buf * KVSTAGE;
#pragma unroll
        for (int i = 0; i < 4; i++) {
            const int e = tid + i * 128;              // 0..511
            const int r = e >> 3, sg = e & 7;
            const size_t go = (size_t)(j0 + r) * DK_ + sg * 8;
            const uint32_t so = (uint32_t)(r * ASTR + sg * 16);
            cp16(kb + 0*KVTILE + so, Kh + go);
            cp16(kb + 1*KVTILE + so, Kl + go);
            cp16(kb + 2*KVTILE + so, Vp + go);
        }
    };

#pragma unroll
    for (int i = 0; i < 8; i++) {
        const int e = tid + i * 128;                  // 0..1023
        const int r = e >> 3, sg = e & 7;
        const size_t go = (size_t)r * DK_ + sg * 8;
        const uint32_t so = (uint32_t)(r * ASTR + sg * 16);
        cp16(sb + SQH + so, Qh + go);
        cp16(sb + SQL + so, Ql + go);
    }
    ldkv(0, 0); CP_COMMIT();
    ldkv(1, 1); CP_COMMIT();

    const int rr = lane & 7, qq = lane >> 3;
    const uint32_t qa_base = (uint32_t)((w*32 + rr + (qq & 1)*8) * ASTR + (qq >> 1)*16);
    const uint32_t kb_row = (uint32_t)(((qq >> 1)*8 + rr) * ASTR + (qq & 1)*16);
    const uint32_t vb_row = (uint32_t)(((qq & 1)*8 + rr) * ASTR + (qq >> 1)*16);

    uint32_t qh[2][4][4], ql[2][4][4];                // f = m16-frag (rows +0, +16)
    float ctx[2][8][4];
#pragma unroll
    for (int f = 0; f < 2; f++)
#pragma unroll
        for (int j = 0; j < 8; j++)
#pragma unroll
            for (int t = 0; t < 4; t++) ctx[f][j][t] = 0.f;
    float mrow[2][2] = {{-1e30f,-1e30f},{-1e30f,-1e30f}};
    float lrow[2][2] = {{0.f,0.f},{0.f,0.f}};

    const int rbase = q0 + w*32 + (lane >> 2);

    for (int c = 0; c < iters; c++) {
        CP_WAIT1();
        __syncthreads();
        if (c == 0) {
#pragma unroll
            for (int f = 0; f < 2; f++)
#pragma unroll
                for (int ks = 0; ks < 4; ks++) {
                    ldm4(qh[f][ks], sb + SQH + qa_base + (uint32_t)f*16*ASTR + ks*32);
                    ldm4(ql[f][ks], sb + SQL + qa_base + (uint32_t)f*16*ASTR + ks*32);
                }
        }
        const uint32_t kb = sb + SKV + (uint32_t)(c & 1) * KVSTAGE;

        // ---- S = Q K^T (3-pass bf16 split; logits already in log2 units) ----
        float s[2][8][4];
#pragma unroll
        for (int f = 0; f < 2; f++)
#pragma unroll
            for (int j = 0; j < 8; j++)
#pragma unroll
                for (int t = 0; t < 4; t++) s[f][j][t] = 0.f;

#pragma unroll
        for (int ks = 0; ks < 4; ks++) {
#pragma unroll
            for (int jn = 0; jn < 4; jn++) {
                uint32_t kh4[4], kl4[4];
                const uint32_t off = (uint32_t)(jn*16*ASTR) + kb_row + ks*32;
                ldm4(kh4, kb + 0*KVTILE + off);
#pragma unroll
                for (int f = 0; f < 2; f++) {
                    mma_bf16(s[f][2*jn],   qh[f][ks], kh4[0], kh4[1]);
                    mma_bf16(s[f][2*jn+1], qh[f][ks], kh4[2], kh4[3]);
                    mma_bf16(s[f][2*jn],   ql[f][ks], kh4[0], kh4[1]);
                    mma_bf16(s[f][2*jn+1], ql[f][ks], kh4[2], kh4[3]);
                }
                ldm4(kl4, kb + 1*KVTILE + off);
#pragma unroll
                for (int f = 0; f < 2; f++) {
                    mma_bf16(s[f][2*jn],   qh[f][ks], kl4[0], kl4[1]);
                    mma_bf16(s[f][2*jn+1], qh[f][ks], kl4[2], kl4[3]);
                }
            }
        }

        // ---- causal mask ----
        const int j0 = c * 64;
        if (j0 + 63 > rbase) {
#pragma unroll
            for (int f = 0; f < 2; f++) {
                const int r1g = rbase + f*16, r2g = r1g + 8;
#pragma unroll
                for (int j = 0; j < 8; j++) {
                    const int cg = j0 + j*8 + (lane & 3)*2;
                    if (cg     > r1g) s[f][j][0] = -1e30f;
                    if (cg + 1 > r1g) s[f][j][1] = -1e30f;
                    if (cg     > r2g) s[f][j][2] = -1e30f;
                    if (cg + 1 > r2g) s[f][j][3] = -1e30f;
                }
            }
        }

        // ---- online softmax (base-2) + fp16 P pack ----
        uint32_t p16[2][4][4];
#pragma unroll
        for (int f = 0; f < 2; f++) {
            float mt1 = s[f][0][0], mt2 = s[f][0][2];
#pragma unroll
            for (int j = 0; j < 8; j++) {
                mt1 = fmaxf(mt1, fmaxf(s[f][j][0], s[f][j][1]));
                mt2 = fmaxf(mt2, fmaxf(s[f][j][2], s[f][j][3]));
            }
            mt1 = fmaxf(mt1, __shfl_xor_sync(0xffffffffu, mt1, 1));
            mt1 = fmaxf(mt1, __shfl_xor_sync(0xffffffffu, mt1, 2));
            mt2 = fmaxf(mt2, __shfl_xor_sync(0xffffffffu, mt2, 1));
            mt2 = fmaxf(mt2, __shfl_xor_sync(0xffffffffu, mt2, 2));
            const float mn1 = fmaxf(mrow[f][0], mt1), mn2 = fmaxf(mrow[f][1], mt2);
            const float co1 = exp2f(mrow[f][0] - mn1), co2 = exp2f(mrow[f][1] - mn2);

            float ps1 = 0.f, ps2 = 0.f;
#pragma unroll
            for (int j = 0; j < 8; j++) {
                s[f][j][0] = exp2f(s[f][j][0] - mn1);
                s[f][j][1] = exp2f(s[f][j][1] - mn1);
                s[f][j][2] = exp2f(s[f][j][2] - mn2);
                s[f][j][3] = exp2f(s[f][j][3] - mn2);
                ps1 += s[f][j][0] + s[f][j][1];
                ps2 += s[f][j][2] + s[f][j][3];
            }
            ps1 += __shfl_xor_sync(0xffffffffu, ps1, 1);
            ps1 += __shfl_xor_sync(0xffffffffu, ps1, 2);
            ps2 += __shfl_xor_sync(0xffffffffu, ps2, 1);
            ps2 += __shfl_xor_sync(0xffffffffu, ps2, 2);
            lrow[f][0] = lrow[f][0] * co1 + ps1;  mrow[f][0] = mn1;
            lrow[f][1] = lrow[f][1] * co2 + ps2;  mrow[f][1] = mn2;

#pragma unroll
            for (int j = 0; j < 8; j++) {
                ctx[f][j][0] *= co1; ctx[f][j][1] *= co1;
                ctx[f][j][2] *= co2; ctx[f][j][3] *= co2;
            }

#pragma unroll
            for (int ks = 0; ks < 4; ks++) {
                p16[f][ks][0] = pkf16(s[f][2*ks][0],   s[f][2*ks][1]);
                p16[f][ks][1] = pkf16(s[f][2*ks][2],   s[f][2*ks][3]);
                p16[f][ks][2] = pkf16(s[f][2*ks+1][0], s[f][2*ks+1][1]);
                p16[f][ks][3] = pkf16(s[f][2*ks+1][2], s[f][2*ks+1][3]);
            }
        }

        // ---- ctx += P V (single fp16 pass), V via ldmatrix.trans ----
#pragma unroll
        for (int ks = 0; ks < 4; ks++) {
#pragma unroll
            for (int jd = 0; jd < 4; jd++) {
                uint32_t v4[4];
                const uint32_t off = (uint32_t)(ks*16*ASTR) + vb_row + jd*32;
                ldm4t(v4, kb + 2*KVTILE + off);
#pragma unroll
                for (int f = 0; f < 2; f++) {
                    mma_f16(ctx[f][2*jd],   p16[f][ks], v4[0], v4[1]);
                    mma_f16(ctx[f][2*jd+1], p16[f][ks], v4[2], v4[3]);
                }
            }
        }

        __syncthreads();
        if (c + 2 < iters) ldkv(c + 2, c & 1);
        CP_COMMIT();
    }

    // ---- epilogue: normalize, write ctx single fp16 to GEMM slot 3 ----
    const int b = bh >> 4, h = bh & 15;
    __half* dst = g_a16[3];
#pragma unroll
    for (int f = 0; f < 2; f++) {
        const float i1 = 1.0f / lrow[f][0], i2 = 1.0f / lrow[f][1];
        const int r1g = rbase + f*16, r2g = r1g + 8;
#pragma unroll
        for (int j = 0; j < 8; j++) {
            const int col = h*64 + j*8 + (lane & 3)*2;
            const size_t o1 = ((size_t)(b * S_ + r1g)) * DM_ + col;
            *(uint32_t*)(dst + o1) = pkf16(ctx[f][j][0] * i1, ctx[f][j][1] * i1);
            const size_t o2 = ((size_t)(b * S_ + r2g)) * DM_ + col;
            *(uint32_t*)(dst + o2) = pkf16(ctx[f][j][2] * i2, ctx[f][j][3] * i2);
        }
    }
}

// ---------------------------------------------------------------------------
extern "C" void kernel_launch(void* const* d_in, const int* in_sizes, int n_in,
                              void* d_out, int out_size)
{
    const float* xq = (const float*)d_in[0];
    const float* xk = (const float*)d_in[1];
    const float* xv = (const float*)d_in[2];
    const float* wq = (const float*)d_in[5];
    const float* wk = (const float*)d_in[6];
    const float* wv = (const float*)d_in[7];
    const float* wo = (const float*)d_in[8];
    float* out = (float*)d_out;

    cudaFuncSetAttribute(gemm_mma<0>, cudaFuncAttributeMaxDynamicSharedMemorySize, GEMM_SMEM);
    cudaFuncSetAttribute(gemm_mma<1>, cudaFuncAttributeMaxDynamicSharedMemorySize, GEMM_SMEM);
    cudaFuncSetAttribute(attn_mma,    cudaFuncAttributeMaxDynamicSharedMemorySize, ATTN_SMEM);

    conv_w<<<dim3(DM_ / 32, DM_ / 32, 4), 256>>>(wq, wk, wv, wo);
    conv_a3<<<dim3((M_TOT * DM_) / (256 * 4), 1, 3), 256>>>(xq, xk, xv);

    // fused QKV projections (blockIdx.z = slot)
    gemm_mma<0><<<dim3(DM_ / 256, M_TOT / 128, 3), 256, GEMM_SMEM>>>(0, 0, nullptr);

    attn_mma<<<dim3(S_ / 128, BH_), 128, ATTN_SMEM>>>();

    gemm_mma<1><<<dim3(DM_ / 256, M_TOT / 128), 256, GEMM_SMEM>>>(3, 3, out);
}